// round 2
// baseline (speedup 1.0000x reference)
#include <cuda_runtime.h>
#include <cuda_bf16.h>

// Problem constants
#define SEQ 4096
#define DIM 1024

// Scratch (allocation-free rule: __device__ globals)
__device__ float g_Q[SEQ * DIM];
__device__ float g_K[SEQ * DIM];
__device__ float g_V[SEQ * DIM];   // projected V, later scaled in-place by 1/rowsum
__device__ float g_E[(size_t)SEQ * SEQ];
__device__ float g_r[SEQ];

// ---------------------------------------------------------------------------
// Classic 128x128x8 SGEMM, 256 threads, 8x8 per-thread tile, float4 loads.
// TRANSB=false : B is [K,N] row-major.   TRANSB=true : B is [N,K] row-major.
// MODE 0: C = A@B + bias[n]
// MODE 1: C = exp((A@B)/1024)
// MODE 2: C = A@B
// ---------------------------------------------------------------------------
#define BM 128
#define BN 128
#define BK 8
#define TM 8
#define TN 8

template <bool TRANSB, int MODE>
__global__ __launch_bounds__(256, 2)
void sgemm_kernel(const float* __restrict__ A, const float* __restrict__ B,
                  const float* __restrict__ bias, float* __restrict__ C,
                  int M, int N, int K) {
    __shared__ float As[BK][BM];
    __shared__ float Bs[BK][BN];

    const int tid = threadIdx.x;
    const int bm = blockIdx.y * BM;
    const int bn = blockIdx.x * BN;

    const int trow = (tid >> 4) * TM;   // 0..120
    const int tcol = (tid & 15) * TN;   // 0..120

    float acc[TM][TN];
#pragma unroll
    for (int i = 0; i < TM; i++)
#pragma unroll
        for (int j = 0; j < TN; j++) acc[i][j] = 0.0f;

    // A-load indices: 128 rows x 8 k, one float4 per thread
    const int a_m = tid >> 1;
    const int a_k = (tid & 1) * 4;

    for (int k0 = 0; k0 < K; k0 += BK) {
        // ---- load A tile (transposed into As[k][m]) ----
        {
            float4 v = *reinterpret_cast<const float4*>(
                &A[(size_t)(bm + a_m) * K + (k0 + a_k)]);
            As[a_k + 0][a_m] = v.x;
            As[a_k + 1][a_m] = v.y;
            As[a_k + 2][a_m] = v.z;
            As[a_k + 3][a_m] = v.w;
        }
        // ---- load B tile ----
        if (TRANSB) {
            // B is [N,K]; tile: 128 n-rows x 8 k, transpose into Bs[k][n]
            const int b_n = tid >> 1;
            const int b_k = (tid & 1) * 4;
            float4 v = *reinterpret_cast<const float4*>(
                &B[(size_t)(bn + b_n) * K + (k0 + b_k)]);
            Bs[b_k + 0][b_n] = v.x;
            Bs[b_k + 1][b_n] = v.y;
            Bs[b_k + 2][b_n] = v.z;
            Bs[b_k + 3][b_n] = v.w;
        } else {
            // B is [K,N]; tile: 8 k-rows x 128 n, direct vector copy
            const int b_k = tid >> 5;
            const int b_n = (tid & 31) * 4;
            float4 v = *reinterpret_cast<const float4*>(
                &B[(size_t)(k0 + b_k) * N + (bn + b_n)]);
            *reinterpret_cast<float4*>(&Bs[b_k][b_n]) = v;
        }
        __syncthreads();

#pragma unroll
        for (int kk = 0; kk < BK; kk++) {
            float ra[TM], rb[TN];
            *reinterpret_cast<float4*>(&ra[0]) =
                *reinterpret_cast<const float4*>(&As[kk][trow]);
            *reinterpret_cast<float4*>(&ra[4]) =
                *reinterpret_cast<const float4*>(&As[kk][trow + 4]);
            *reinterpret_cast<float4*>(&rb[0]) =
                *reinterpret_cast<const float4*>(&Bs[kk][tcol]);
            *reinterpret_cast<float4*>(&rb[4]) =
                *reinterpret_cast<const float4*>(&Bs[kk][tcol + 4]);
#pragma unroll
            for (int i = 0; i < TM; i++)
#pragma unroll
                for (int j = 0; j < TN; j++)
                    acc[i][j] = fmaf(ra[i], rb[j], acc[i][j]);
        }
        __syncthreads();
    }

    // ---- epilogue ----
    float bv[TN];
    if (MODE == 0) {
#pragma unroll
        for (int j = 0; j < TN; j++) bv[j] = bias[bn + tcol + j];
    }
#pragma unroll
    for (int i = 0; i < TM; i++) {
        float outv[TN];
#pragma unroll
        for (int j = 0; j < TN; j++) {
            float v = acc[i][j];
            if (MODE == 0) v += bv[j];
            if (MODE == 1) v = __expf(v * (1.0f / 1024.0f));
            outv[j] = v;
        }
        float* crow = &C[(size_t)(bm + trow + i) * N + (bn + tcol)];
        *reinterpret_cast<float4*>(crow) =
            *reinterpret_cast<const float4*>(&outv[0]);
        *reinterpret_cast<float4*>(crow + 4) =
            *reinterpret_cast<const float4*>(&outv[4]);
    }
}

// ---------------------------------------------------------------------------
// Row-sum of E: one block per row
// ---------------------------------------------------------------------------
__global__ void rowsum_kernel(const float* __restrict__ E, float* __restrict__ r) {
    const int row = blockIdx.x;
    const float4* p = reinterpret_cast<const float4*>(E + (size_t)row * SEQ);
    float s = 0.0f;
    for (int i = threadIdx.x; i < SEQ / 4; i += 256) {
        float4 v = p[i];
        s += (v.x + v.y) + (v.z + v.w);
    }
    __shared__ float sm[8];
#pragma unroll
    for (int o = 16; o > 0; o >>= 1) s += __shfl_down_sync(0xFFFFFFFFu, s, o);
    if ((threadIdx.x & 31) == 0) sm[threadIdx.x >> 5] = s;
    __syncthreads();
    if (threadIdx.x < 8) {
        s = sm[threadIdx.x];
#pragma unroll
        for (int o = 4; o > 0; o >>= 1) s += __shfl_down_sync(0xFFu, s, o);
        if (threadIdx.x == 0) r[row] = s;
    }
}

// ---------------------------------------------------------------------------
// V'[j][d] = V[j][d] / r[j]   (in-place; V rewritten by proj each replay)
// ---------------------------------------------------------------------------
__global__ void scale_v_kernel(float* __restrict__ V, const float* __restrict__ r) {
    const int j = blockIdx.x;
    const float inv = 1.0f / r[j];
    float4* p = reinterpret_cast<float4*>(V + (size_t)j * DIM);
    float4 v = p[threadIdx.x];  // 256 threads * float4 = 1024 = DIM
    v.x *= inv; v.y *= inv; v.z *= inv; v.w *= inv;
    p[threadIdx.x] = v;
}

// ---------------------------------------------------------------------------
// Launch: query,key,value,Wq,bq,Wk,bk,Wv,bv  -> out [SEQ, DIM] fp32
// ---------------------------------------------------------------------------
extern "C" void kernel_launch(void* const* d_in, const int* in_sizes, int n_in,
                              void* d_out, int out_size) {
    const float* query = (const float*)d_in[0];
    const float* key   = (const float*)d_in[1];
    const float* value = (const float*)d_in[2];
    const float* Wq    = (const float*)d_in[3];
    const float* bq    = (const float*)d_in[4];
    const float* Wk    = (const float*)d_in[5];
    const float* bk    = (const float*)d_in[6];
    const float* Wv    = (const float*)d_in[7];
    const float* bv    = (const float*)d_in[8];
    float* out = (float*)d_out;

    float *Qp, *Kp, *Vp, *Ep, *rp;
    cudaGetSymbolAddress((void**)&Qp, g_Q);
    cudaGetSymbolAddress((void**)&Kp, g_K);
    cudaGetSymbolAddress((void**)&Vp, g_V);
    cudaGetSymbolAddress((void**)&Ep, g_E);
    cudaGetSymbolAddress((void**)&rp, g_r);

    dim3 block(256);
    dim3 gridProj(DIM / BN, SEQ / BM);   // 8 x 32
    dim3 gridScores(SEQ / BN, SEQ / BM); // 32 x 32
    dim3 gridOut(DIM / BN, SEQ / BM);    // 8 x 32

    // Projections: X @ W + b
    sgemm_kernel<false, 0><<<gridProj, block>>>(query, Wq, bq, Qp, SEQ, DIM, DIM);
    sgemm_kernel<false, 0><<<gridProj, block>>>(key,   Wk, bk, Kp, SEQ, DIM, DIM);
    sgemm_kernel<false, 0><<<gridProj, block>>>(value, Wv, bv, Vp, SEQ, DIM, DIM);

    // E = exp((Q @ K^T) / 1024)
    sgemm_kernel<true, 1><<<gridScores, block>>>(Qp, Kp, nullptr, Ep, SEQ, SEQ, DIM);

    // r[i] = sum_j E[i][j]
    rowsum_kernel<<<SEQ, block>>>(Ep, rp);

    // V'[j] = V[j] / r[j]
    scale_v_kernel<<<SEQ, block>>>(Vp, rp);

    // out = E @ V'
    sgemm_kernel<false, 2><<<gridOut, block>>>(Ep, Vp, nullptr, out, SEQ, DIM, SEQ);
}

// round 4
// speedup vs baseline: 1.4595x; 1.4595x over previous
#include <cuda_runtime.h>
#include <cuda_bf16.h>
#include <cstdint>

#define SEQ 4096
#define DIM 1024
typedef __nv_bfloat16 bf16;

// ---------------- scratch (__device__ globals; allocation-free) ----------------
__device__ __align__(256) bf16 g_xqh[SEQ*DIM], g_xql[SEQ*DIM];
__device__ __align__(256) bf16 g_xkh[SEQ*DIM], g_xkl[SEQ*DIM];
__device__ __align__(256) bf16 g_xvh[SEQ*DIM], g_xvl[SEQ*DIM];
__device__ __align__(256) bf16 g_WqTh[DIM*DIM], g_WqTl[DIM*DIM];
__device__ __align__(256) bf16 g_WkTh[DIM*DIM], g_WkTl[DIM*DIM];
__device__ __align__(256) bf16 g_WvTh[DIM*DIM], g_WvTl[DIM*DIM];
__device__ __align__(256) bf16 g_Qh[SEQ*DIM], g_Ql[SEQ*DIM];
__device__ __align__(256) bf16 g_Kh[SEQ*DIM], g_Kl[SEQ*DIM];
__device__ __align__(256) float g_VTf[(size_t)DIM*SEQ];
__device__ __align__(256) bf16 g_VTh[(size_t)DIM*SEQ], g_VTl[(size_t)DIM*SEQ];
__device__ __align__(256) bf16 g_Eh[(size_t)SEQ*SEQ], g_El[(size_t)SEQ*SEQ];
__device__ float g_rinv[SEQ];

// ---------------- helpers ----------------
__device__ __forceinline__ uint32_t smem_u32(const void* p) {
    uint32_t a;
    asm("{ .reg .u64 t; cvta.to.shared.u64 t, %1; cvt.u32.u64 %0, t; }" : "=r"(a) : "l"(p));
    return a;
}
__device__ __forceinline__ void cp16(uint32_t s, const void* g) {
    asm volatile("cp.async.cg.shared.global [%0], [%1], 16;" :: "r"(s), "l"(g) : "memory");
}
#define CP_COMMIT() asm volatile("cp.async.commit_group;" ::: "memory")
#define CP_WAIT1()  asm volatile("cp.async.wait_group 1;" ::: "memory")
#define CP_WAIT0()  asm volatile("cp.async.wait_group 0;" ::: "memory")

__device__ __forceinline__ void mma_bf16(float* c, const uint32_t* a, const uint32_t* b) {
    asm volatile(
        "mma.sync.aligned.m16n8k16.row.col.f32.bf16.bf16.f32 "
        "{%0,%1,%2,%3}, {%4,%5,%6,%7}, {%8,%9}, {%0,%1,%2,%3};"
        : "+f"(c[0]), "+f"(c[1]), "+f"(c[2]), "+f"(c[3])
        : "r"(a[0]), "r"(a[1]), "r"(a[2]), "r"(a[3]), "r"(b[0]), "r"(b[1]));
}

// ---------------------------------------------------------------------------
// bf16 HMMA GEMM: D[M,N] = sum_p A_p[M,KP] @ B_p[N,KP]^T  (fp32 accum)
// Block 128x128, BK=64, 256 thr (8 warps, 2x4), 2-stage cp.async pipeline.
// SMEM row stride 144B (conflict-free fragment loads).
// MODE 0: bf16 hi/lo pair = acc + bias[n]       (Q/K proj)
// MODE 1: f32 = acc + bias[m]                   (V^T proj)
// MODE 2: bf16 hi/lo pair = exp(acc/1024)       (E)
// MODE 3: f32 = acc                             (out)
// ---------------------------------------------------------------------------
#define STRIDE 144
#define STAGE_BYTES (256 * STRIDE)          // A(128 rows) + B(128 rows)
#define SMEM_DYN (2 * STAGE_BYTES)          // 73728

template <int KP, int MODE>
__global__ void __launch_bounds__(256, 1)
gemm_mma(const bf16* __restrict__ A0, const bf16* __restrict__ B0,
         const bf16* __restrict__ A1, const bf16* __restrict__ B1,
         const bf16* __restrict__ A2, const bf16* __restrict__ B2,
         int npass, const float* __restrict__ bias,
         void* __restrict__ Cp0, void* __restrict__ Cp1, int ldc)
{
    extern __shared__ char smem[];
    const uint32_t sb = smem_u32(smem);
    const int tid = threadIdx.x;
    const int warp = tid >> 5, lane = tid & 31;
    const int wm = warp & 1;          // 0..1  (64-row slabs)
    const int wn = warp >> 1;         // 0..3  (32-col slabs)
    const size_t bm = (size_t)blockIdx.y * 128, bn = (size_t)blockIdx.x * 128;

    constexpr int KST = KP / 64;
    const int ktot = npass * KST;

    // loader geometry: thread -> (row, 64B half-row)
    const int lr = tid >> 1;
    const int lc = (tid & 1) * 64;

    auto load_stage = [&](int buf, int kt) {
        int p = kt / KST, kk = kt - p * KST;
        const bf16* A = (p == 0) ? A0 : (p == 1 ? A1 : A2);
        const bf16* B = (p == 0) ? B0 : (p == 1 ? B1 : B2);
        const char* ag = (const char*)(A + (bm + lr) * KP + kk * 64) + lc;
        const char* bg = (const char*)(B + (bn + lr) * KP + kk * 64) + lc;
        uint32_t sa = sb + buf * STAGE_BYTES + lr * STRIDE + lc;
        uint32_t sbB = sa + 128 * STRIDE;
#pragma unroll
        for (int i = 0; i < 4; i++) cp16(sa  + i * 16, ag + i * 16);
#pragma unroll
        for (int i = 0; i < 4; i++) cp16(sbB + i * 16, bg + i * 16);
    };

    float acc[4][4][4];
#pragma unroll
    for (int mi = 0; mi < 4; mi++)
#pragma unroll
        for (int ni = 0; ni < 4; ni++)
#pragma unroll
            for (int q = 0; q < 4; q++) acc[mi][ni][q] = 0.0f;

    load_stage(0, 0);
    CP_COMMIT();

    const int fr = lane >> 2;            // 0..7
    const int fc = (lane & 3) * 4;       // byte offset of b32 pair within k16

    for (int kt = 0; kt < ktot; kt++) {
        const int buf = kt & 1;
        if (kt + 1 < ktot) { load_stage((kt + 1) & 1, kt + 1); CP_COMMIT(); CP_WAIT1(); }
        else               { CP_WAIT0(); }
        __syncthreads();

        const char* sA = smem + buf * STAGE_BYTES;
        const char* sB = sA + 128 * STRIDE;
#pragma unroll
        for (int ks = 0; ks < 4; ks++) {
            const int kb = ks * 32 + fc;   // byte offset along k
            uint32_t a[4][4], b[4][2];
#pragma unroll
            for (int mi = 0; mi < 4; mi++) {
                const char* p = sA + (wm * 64 + mi * 16 + fr) * STRIDE + kb;
                a[mi][0] = *(const uint32_t*)(p);
                a[mi][1] = *(const uint32_t*)(p + 8 * STRIDE);
                a[mi][2] = *(const uint32_t*)(p + 16);
                a[mi][3] = *(const uint32_t*)(p + 8 * STRIDE + 16);
            }
#pragma unroll
            for (int ni = 0; ni < 4; ni++) {
                const char* p = sB + (wn * 32 + ni * 8 + fr) * STRIDE + kb;
                b[ni][0] = *(const uint32_t*)(p);
                b[ni][1] = *(const uint32_t*)(p + 16);
            }
#pragma unroll
            for (int mi = 0; mi < 4; mi++)
#pragma unroll
                for (int ni = 0; ni < 4; ni++)
                    mma_bf16(acc[mi][ni], a[mi], b[ni]);
        }
        __syncthreads();
    }

    // ---- epilogue ----
    const int row0 = (int)bm + wm * 64 + (lane >> 2);
    const int col0 = (int)bn + wn * 32 + (lane & 3) * 2;
#pragma unroll
    for (int mi = 0; mi < 4; mi++) {
#pragma unroll
        for (int ni = 0; ni < 4; ni++) {
#pragma unroll
            for (int h = 0; h < 2; h++) {
                int r = row0 + mi * 16 + h * 8;
                int c = col0 + ni * 8;
                float v0 = acc[mi][ni][h * 2 + 0];
                float v1 = acc[mi][ni][h * 2 + 1];
                size_t gi = (size_t)r * ldc + c;
                if (MODE == 0) {
                    v0 += bias[c]; v1 += bias[c + 1];
                    bf16 h0 = __float2bfloat16(v0), h1 = __float2bfloat16(v1);
                    *(__nv_bfloat162*)((bf16*)Cp0 + gi) = __nv_bfloat162(h0, h1);
                    *(__nv_bfloat162*)((bf16*)Cp1 + gi) = __nv_bfloat162(
                        __float2bfloat16(v0 - __bfloat162float(h0)),
                        __float2bfloat16(v1 - __bfloat162float(h1)));
                } else if (MODE == 1) {
                    float bm_b = bias[r];
                    *(float2*)((float*)Cp0 + gi) = make_float2(v0 + bm_b, v1 + bm_b);
                } else if (MODE == 2) {
                    v0 = __expf(v0 * (1.0f / 1024.0f));
                    v1 = __expf(v1 * (1.0f / 1024.0f));
                    bf16 h0 = __float2bfloat16(v0), h1 = __float2bfloat16(v1);
                    *(__nv_bfloat162*)((bf16*)Cp0 + gi) = __nv_bfloat162(h0, h1);
                    *(__nv_bfloat162*)((bf16*)Cp1 + gi) = __nv_bfloat162(
                        __float2bfloat16(v0 - __bfloat162float(h0)),
                        __float2bfloat16(v1 - __bfloat162float(h1)));
                } else {
                    *(float2*)((float*)Cp0 + gi) = make_float2(v0, v1);
                }
            }
        }
    }
}

// ---------------- prep / elementwise ----------------
__global__ void split_kernel(const float* __restrict__ X, bf16* __restrict__ H,
                             bf16* __restrict__ L) {
    size_t i = ((size_t)blockIdx.x * 256 + threadIdx.x) * 4;
    float4 v = *(const float4*)(X + i);
    float f[4] = {v.x, v.y, v.z, v.w};
#pragma unroll
    for (int j = 0; j < 4; j++) {
        bf16 h = __float2bfloat16(f[j]);
        H[i + j] = h;
        L[i + j] = __float2bfloat16(f[j] - __bfloat162float(h));
    }
}

__global__ void wtrans_kernel(const float* __restrict__ W, bf16* __restrict__ TH,
                              bf16* __restrict__ TL) {
    __shared__ float t[32][33];
    int k0 = blockIdx.y * 32, n0 = blockIdx.x * 32;
    int tx = threadIdx.x, ty = threadIdx.y;
    for (int r = ty; r < 32; r += 8) t[r][tx] = W[(size_t)(k0 + r) * DIM + n0 + tx];
    __syncthreads();
    for (int r = ty; r < 32; r += 8) {
        float v = t[tx][r];
        size_t gi = (size_t)(n0 + r) * DIM + (k0 + tx);
        bf16 h = __float2bfloat16(v);
        TH[gi] = h;
        TL[gi] = __float2bfloat16(v - __bfloat162float(h));
    }
}

__device__ __forceinline__ float sum2bf(uint32_t u) {
    __nv_bfloat162 b = *reinterpret_cast<__nv_bfloat162*>(&u);
    float2 f = __bfloat1622float2(b);
    return f.x + f.y;
}
__global__ void rowsum_kernel(const bf16* __restrict__ Eh, const bf16* __restrict__ El,
                              float* __restrict__ rinv) {
    int row = blockIdx.x;
    const uint4* ph = (const uint4*)(Eh + (size_t)row * SEQ);
    const uint4* pl = (const uint4*)(El + (size_t)row * SEQ);
    float s = 0.f;
    for (int i = threadIdx.x; i < SEQ / 8; i += 256) {
        uint4 a = ph[i], b = pl[i];
        s += sum2bf(a.x) + sum2bf(a.y) + sum2bf(a.z) + sum2bf(a.w);
        s += sum2bf(b.x) + sum2bf(b.y) + sum2bf(b.z) + sum2bf(b.w);
    }
    __shared__ float sm[8];
#pragma unroll
    for (int o = 16; o > 0; o >>= 1) s += __shfl_down_sync(0xFFFFFFFFu, s, o);
    if ((threadIdx.x & 31) == 0) sm[threadIdx.x >> 5] = s;
    __syncthreads();
    if (threadIdx.x < 8) {
        s = sm[threadIdx.x];
#pragma unroll
        for (int o = 4; o > 0; o >>= 1) s += __shfl_down_sync(0xFFu, s, o);
        if (threadIdx.x == 0) rinv[row] = 1.0f / s;
    }
}

__global__ void scalesplit_kernel(const float* __restrict__ VT,
                                  const float* __restrict__ rinv,
                                  bf16* __restrict__ H, bf16* __restrict__ L) {
    size_t i = ((size_t)blockIdx.x * 256 + threadIdx.x) * 4;
    int j = (int)(i % SEQ);
    float4 v = *(const float4*)(VT + i);
    float4 r = *(const float4*)(rinv + j);
    float f[4] = {v.x * r.x, v.y * r.y, v.z * r.z, v.w * r.w};
#pragma unroll
    for (int q = 0; q < 4; q++) {
        bf16 h = __float2bfloat16(f[q]);
        H[i + q] = h;
        L[i + q] = __float2bfloat16(f[q] - __bfloat162float(h));
    }
}

// ---------------- launch ----------------
extern "C" void kernel_launch(void* const* d_in, const int* in_sizes, int n_in,
                              void* d_out, int out_size) {
    const float* query = (const float*)d_in[0];
    const float* key   = (const float*)d_in[1];
    const float* value = (const float*)d_in[2];
    const float* Wq    = (const float*)d_in[3];
    const float* bq    = (const float*)d_in[4];
    const float* Wk    = (const float*)d_in[5];
    const float* bk    = (const float*)d_in[6];
    const float* Wv    = (const float*)d_in[7];
    const float* bv    = (const float*)d_in[8];
    float* out = (float*)d_out;

    bf16 *xqh,*xql,*xkh,*xkl,*xvh,*xvl,*WqTh,*WqTl,*WkTh,*WkTl,*WvTh,*WvTl;
    bf16 *Qh,*Ql,*Kh,*Kl,*VTh,*VTl,*Eh,*El;
    float *VTf,*rinv;
    cudaGetSymbolAddress((void**)&xqh, g_xqh);   cudaGetSymbolAddress((void**)&xql, g_xql);
    cudaGetSymbolAddress((void**)&xkh, g_xkh);   cudaGetSymbolAddress((void**)&xkl, g_xkl);
    cudaGetSymbolAddress((void**)&xvh, g_xvh);   cudaGetSymbolAddress((void**)&xvl, g_xvl);
    cudaGetSymbolAddress((void**)&WqTh, g_WqTh); cudaGetSymbolAddress((void**)&WqTl, g_WqTl);
    cudaGetSymbolAddress((void**)&WkTh, g_WkTh); cudaGetSymbolAddress((void**)&WkTl, g_WkTl);
    cudaGetSymbolAddress((void**)&WvTh, g_WvTh); cudaGetSymbolAddress((void**)&WvTl, g_WvTl);
    cudaGetSymbolAddress((void**)&Qh, g_Qh);     cudaGetSymbolAddress((void**)&Ql, g_Ql);
    cudaGetSymbolAddress((void**)&Kh, g_Kh);     cudaGetSymbolAddress((void**)&Kl, g_Kl);
    cudaGetSymbolAddress((void**)&VTf, g_VTf);
    cudaGetSymbolAddress((void**)&VTh, g_VTh);   cudaGetSymbolAddress((void**)&VTl, g_VTl);
    cudaGetSymbolAddress((void**)&Eh, g_Eh);     cudaGetSymbolAddress((void**)&El, g_El);
    cudaGetSymbolAddress((void**)&rinv, g_rinv);

    cudaFuncSetAttribute(gemm_mma<1024,0>, cudaFuncAttributeMaxDynamicSharedMemorySize, SMEM_DYN);
    cudaFuncSetAttribute(gemm_mma<1024,1>, cudaFuncAttributeMaxDynamicSharedMemorySize, SMEM_DYN);
    cudaFuncSetAttribute(gemm_mma<1024,2>, cudaFuncAttributeMaxDynamicSharedMemorySize, SMEM_DYN);
    cudaFuncSetAttribute(gemm_mma<4096,3>, cudaFuncAttributeMaxDynamicSharedMemorySize, SMEM_DYN);

    // prep: hi/lo splits of inputs, hi/lo transposed weights
    split_kernel<<<SEQ*DIM/1024, 256>>>(query, xqh, xql);
    split_kernel<<<SEQ*DIM/1024, 256>>>(key,   xkh, xkl);
    split_kernel<<<SEQ*DIM/1024, 256>>>(value, xvh, xvl);
    dim3 wb(32, 8), wg(DIM/32, DIM/32);
    wtrans_kernel<<<wg, wb>>>(Wq, WqTh, WqTl);
    wtrans_kernel<<<wg, wb>>>(Wk, WkTh, WkTl);
    wtrans_kernel<<<wg, wb>>>(Wv, WvTh, WvTl);

    // Q,K projections: 3-pass split -> bf16 hi/lo outputs (+bias[n])
    gemm_mma<1024,0><<<dim3(DIM/128, SEQ/128), 256, SMEM_DYN>>>(
        xqh, WqTh, xql, WqTh, xqh, WqTl, 3, bq, Qh, Ql, DIM);
    gemm_mma<1024,0><<<dim3(DIM/128, SEQ/128), 256, SMEM_DYN>>>(
        xkh, WkTh, xkl, WkTh, xkh, WkTl, 3, bk, Kh, Kl, DIM);

    // V^T = WvT @ value^T + bv[m]  (3-pass, fp32 [DIM,SEQ])
    gemm_mma<1024,1><<<dim3(SEQ/128, DIM/128), 256, SMEM_DYN>>>(
        WvTh, xvh, WvTl, xvh, WvTh, xvl, 3, bv, VTf, nullptr, SEQ);

    // E = exp((Q@K^T)/1024)  (3-pass, bf16 hi/lo [SEQ,SEQ])
    gemm_mma<1024,2><<<dim3(SEQ/128, SEQ/128), 256, SMEM_DYN>>>(
        Qh, Kh, Ql, Kh, Qh, Kl, 3, nullptr, Eh, El, SEQ);

    rowsum_kernel<<<SEQ, 256>>>(Eh, El, rinv);
    scalesplit_kernel<<<(int)((size_t)DIM*SEQ/1024), 256>>>(VTf, rinv, VTh, VTl);

    // out = E @ V'  (3-pass, fp32 [SEQ,DIM])
    gemm_mma<4096,3><<<dim3(DIM/128, SEQ/128), 256, SMEM_DYN>>>(
        Eh, VTh, El, VTh, Eh, VTl, 3, nullptr, out, nullptr, DIM);
}

// round 5
// speedup vs baseline: 2.2113x; 1.5151x over previous
#include <cuda_runtime.h>
#include <cuda_fp16.h>
#include <cstdint>

#define SEQ 4096
#define DIM 1024
typedef __half fp16;

// ---------------- scratch (__device__ globals; allocation-free) ----------------
__device__ __align__(256) fp16 g_xqh[SEQ*DIM];
__device__ __align__(256) fp16 g_xkh[SEQ*DIM];
__device__ __align__(256) fp16 g_xvh[SEQ*DIM], g_xvl[SEQ*DIM];
__device__ __align__(256) fp16 g_WqTh[DIM*DIM];
__device__ __align__(256) fp16 g_WkTh[DIM*DIM];
__device__ __align__(256) fp16 g_WvTh[DIM*DIM], g_WvTl[DIM*DIM];
__device__ __align__(256) fp16 g_Qh[SEQ*DIM];
__device__ __align__(256) fp16 g_Kh[SEQ*DIM];
__device__ __align__(256) float g_VTf[(size_t)DIM*SEQ];
__device__ __align__(256) fp16 g_VTh[(size_t)DIM*SEQ], g_VTl[(size_t)DIM*SEQ];
__device__ __align__(256) fp16 g_Eh[(size_t)SEQ*SEQ], g_El[(size_t)SEQ*SEQ];
__device__ float g_rinv[SEQ];

// ---------------- helpers ----------------
__device__ __forceinline__ uint32_t smem_u32(const void* p) {
    uint32_t a;
    asm("{ .reg .u64 t; cvta.to.shared.u64 t, %1; cvt.u32.u64 %0, t; }" : "=r"(a) : "l"(p));
    return a;
}
__device__ __forceinline__ void cp16(uint32_t s, const void* g) {
    asm volatile("cp.async.cg.shared.global [%0], [%1], 16;" :: "r"(s), "l"(g) : "memory");
}
#define CP_COMMIT() asm volatile("cp.async.commit_group;" ::: "memory")
#define CP_WAIT1()  asm volatile("cp.async.wait_group 1;" ::: "memory")
#define CP_WAIT0()  asm volatile("cp.async.wait_group 0;" ::: "memory")

__device__ __forceinline__ void mma_f16(float* c, const uint32_t* a, const uint32_t* b) {
    asm volatile(
        "mma.sync.aligned.m16n8k16.row.col.f32.f16.f16.f32 "
        "{%0,%1,%2,%3}, {%4,%5,%6,%7}, {%8,%9}, {%0,%1,%2,%3};"
        : "+f"(c[0]), "+f"(c[1]), "+f"(c[2]), "+f"(c[3])
        : "r"(a[0]), "r"(a[1]), "r"(a[2]), "r"(a[3]), "r"(b[0]), "r"(b[1]));
}
__device__ __forceinline__ void ldsm_x4(uint32_t* r, uint32_t addr) {
    asm volatile("ldmatrix.sync.aligned.m8n8.x4.shared.b16 {%0,%1,%2,%3}, [%4];"
        : "=r"(r[0]), "=r"(r[1]), "=r"(r[2]), "=r"(r[3]) : "r"(addr));
}
__device__ __forceinline__ void ldsm_x2(uint32_t* r, uint32_t addr) {
    asm volatile("ldmatrix.sync.aligned.m8n8.x2.shared.b16 {%0,%1}, [%2];"
        : "=r"(r[0]), "=r"(r[1]) : "r"(addr));
}

// ---------------------------------------------------------------------------
// fp16 HMMA GEMM: D[M,N] = sum_p A_p[M,KP] @ B_p[N,KP]^T  (fp32 accum)
// Block 128x128, BK=64, 256 thr (8 warps 2x4), 2-stage cp.async, ldmatrix.
// MODE 0: fp16 = acc + bias[n]              (Q/K proj, hi only)
// MODE 1: f32  = acc + bias[m]              (V^T proj)
// MODE 2: fp16 hi/lo = exp(acc/1024)        (E)
// MODE 3: f32  = acc * (1/4096)             (out; V' pre-scaled by 4096)
// ---------------------------------------------------------------------------
#define STRIDE 144
#define STAGE_BYTES (256 * STRIDE)
#define SMEM_DYN (2 * STAGE_BYTES)

template <int KP, int MODE>
__global__ void __launch_bounds__(256, 1)
gemm_mma(const fp16* __restrict__ A0, const fp16* __restrict__ B0,
         const fp16* __restrict__ A1, const fp16* __restrict__ B1,
         const fp16* __restrict__ A2, const fp16* __restrict__ B2,
         int npass, const float* __restrict__ bias,
         void* __restrict__ Cp0, void* __restrict__ Cp1, int ldc)
{
    extern __shared__ char smem[];
    const uint32_t sb = smem_u32(smem);
    const int tid = threadIdx.x;
    const int warp = tid >> 5, lane = tid & 31;
    const int wm = warp & 1;          // 0..1 (64-row slabs)
    const int wn = warp >> 1;         // 0..3 (32-col slabs)
    const size_t bm = (size_t)blockIdx.y * 128, bn = (size_t)blockIdx.x * 128;

    constexpr int KST = KP / 64;
    const int ktot = npass * KST;

    // loader geometry: thread -> (row, 64B half-row)
    const int lr = tid >> 1;
    const int lc = (tid & 1) * 64;

    auto load_stage = [&](int buf, int kt) {
        int p = kt / KST, kk = kt - p * KST;
        const fp16* A = (p == 0) ? A0 : (p == 1 ? A1 : A2);
        const fp16* B = (p == 0) ? B0 : (p == 1 ? B1 : B2);
        const char* ag = (const char*)(A + (bm + lr) * KP + kk * 64) + lc;
        const char* bg = (const char*)(B + (bn + lr) * KP + kk * 64) + lc;
        uint32_t sa = sb + buf * STAGE_BYTES + lr * STRIDE + lc;
        uint32_t sbB = sa + 128 * STRIDE;
#pragma unroll
        for (int i = 0; i < 4; i++) cp16(sa  + i * 16, ag + i * 16);
#pragma unroll
        for (int i = 0; i < 4; i++) cp16(sbB + i * 16, bg + i * 16);
    };

    float acc[4][4][4];
#pragma unroll
    for (int mi = 0; mi < 4; mi++)
#pragma unroll
        for (int ni = 0; ni < 4; ni++)
#pragma unroll
            for (int q = 0; q < 4; q++) acc[mi][ni][q] = 0.0f;

    load_stage(0, 0);
    CP_COMMIT();

    // ldmatrix per-lane base offsets
    const uint32_t aOff = (uint32_t)(wm * 64 + (lane & 15)) * STRIDE + ((lane >> 4) << 4);
    const uint32_t bOff = (uint32_t)(wn * 32 + (lane & 7)) * STRIDE + (((lane >> 3) & 1) << 4);

    for (int kt = 0; kt < ktot; kt++) {
        const int buf = kt & 1;
        if (kt + 1 < ktot) { load_stage((kt + 1) & 1, kt + 1); CP_COMMIT(); CP_WAIT1(); }
        else               { CP_WAIT0(); }
        __syncthreads();

        const uint32_t sA = sb + buf * STAGE_BYTES;
        const uint32_t sB = sA + 128 * STRIDE;
#pragma unroll
        for (int ks = 0; ks < 4; ks++) {
            uint32_t a[4][4], b[4][2];
#pragma unroll
            for (int mi = 0; mi < 4; mi++)
                ldsm_x4(a[mi], sA + aOff + mi * (16 * STRIDE) + ks * 32);
#pragma unroll
            for (int ni = 0; ni < 4; ni++)
                ldsm_x2(b[ni], sB + bOff + ni * (8 * STRIDE) + ks * 32);
#pragma unroll
            for (int mi = 0; mi < 4; mi++)
#pragma unroll
                for (int ni = 0; ni < 4; ni++)
                    mma_f16(acc[mi][ni], a[mi], b[ni]);
        }
        __syncthreads();
    }

    // ---- epilogue ----
    const int row0 = (int)bm + wm * 64 + (lane >> 2);
    const int col0 = (int)bn + wn * 32 + (lane & 3) * 2;
#pragma unroll
    for (int mi = 0; mi < 4; mi++) {
#pragma unroll
        for (int ni = 0; ni < 4; ni++) {
#pragma unroll
            for (int h = 0; h < 2; h++) {
                int r = row0 + mi * 16 + h * 8;
                int c = col0 + ni * 8;
                float v0 = acc[mi][ni][h * 2 + 0];
                float v1 = acc[mi][ni][h * 2 + 1];
                size_t gi = (size_t)r * ldc + c;
                if (MODE == 0) {
                    v0 += bias[c]; v1 += bias[c + 1];
                    *(__half2*)((fp16*)Cp0 + gi) =
                        __halves2half2(__float2half(v0), __float2half(v1));
                } else if (MODE == 1) {
                    float bb = bias[r];
                    *(float2*)((float*)Cp0 + gi) = make_float2(v0 + bb, v1 + bb);
                } else if (MODE == 2) {
                    v0 = __expf(v0 * (1.0f / 1024.0f));
                    v1 = __expf(v1 * (1.0f / 1024.0f));
                    fp16 h0 = __float2half(v0), h1 = __float2half(v1);
                    *(__half2*)((fp16*)Cp0 + gi) = __halves2half2(h0, h1);
                    *(__half2*)((fp16*)Cp1 + gi) = __halves2half2(
                        __float2half(v0 - __half2float(h0)),
                        __float2half(v1 - __half2float(h1)));
                } else {
                    *(float2*)((float*)Cp0 + gi) =
                        make_float2(v0 * (1.0f / 4096.0f), v1 * (1.0f / 4096.0f));
                }
            }
        }
    }
}

// ---------------- prep / elementwise ----------------
template <bool LO>
__global__ void split_kernel(const float* __restrict__ X, fp16* __restrict__ H,
                             fp16* __restrict__ L) {
    size_t i = ((size_t)blockIdx.x * 256 + threadIdx.x) * 4;
    float4 v = *(const float4*)(X + i);
    float f[4] = {v.x, v.y, v.z, v.w};
#pragma unroll
    for (int j = 0; j < 4; j++) {
        fp16 h = __float2half(f[j]);
        H[i + j] = h;
        if (LO) L[i + j] = __float2half(f[j] - __half2float(h));
    }
}

template <bool LO>
__global__ void wtrans_kernel(const float* __restrict__ W, fp16* __restrict__ TH,
                              fp16* __restrict__ TL) {
    __shared__ float t[32][33];
    int k0 = blockIdx.y * 32, n0 = blockIdx.x * 32;
    int tx = threadIdx.x, ty = threadIdx.y;
    for (int r = ty; r < 32; r += 8) t[r][tx] = W[(size_t)(k0 + r) * DIM + n0 + tx];
    __syncthreads();
    for (int r = ty; r < 32; r += 8) {
        float v = t[tx][r];
        size_t gi = (size_t)(n0 + r) * DIM + (k0 + tx);
        fp16 h = __float2half(v);
        TH[gi] = h;
        if (LO) TL[gi] = __float2half(v - __half2float(h));
    }
}

__device__ __forceinline__ float sum2h(uint32_t u) {
    __half2 b = *reinterpret_cast<__half2*>(&u);
    float2 f = __half22float2(b);
    return f.x + f.y;
}
__global__ void rowsum_kernel(const fp16* __restrict__ Eh, const fp16* __restrict__ El,
                              float* __restrict__ rinv) {
    int row = blockIdx.x;
    const uint4* ph = (const uint4*)(Eh + (size_t)row * SEQ);
    const uint4* pl = (const uint4*)(El + (size_t)row * SEQ);
    float s = 0.f;
    for (int i = threadIdx.x; i < SEQ / 8; i += 256) {
        uint4 a = ph[i], b = pl[i];
        s += sum2h(a.x) + sum2h(a.y) + sum2h(a.z) + sum2h(a.w);
        s += sum2h(b.x) + sum2h(b.y) + sum2h(b.z) + sum2h(b.w);
    }
    __shared__ float sm[8];
#pragma unroll
    for (int o = 16; o > 0; o >>= 1) s += __shfl_down_sync(0xFFFFFFFFu, s, o);
    if ((threadIdx.x & 31) == 0) sm[threadIdx.x >> 5] = s;
    __syncthreads();
    if (threadIdx.x < 8) {
        s = sm[threadIdx.x];
#pragma unroll
        for (int o = 4; o > 0; o >>= 1) s += __shfl_down_sync(0xFFu, s, o);
        if (threadIdx.x == 0) rinv[row] = 4096.0f / s;   // x4096 normalization
    }
}

// V''T[d][j] = VT[d][j] * (4096/r[j]), split hi/lo fp16
__global__ void scalesplit_kernel(const float* __restrict__ VT,
                                  const float* __restrict__ rinv,
                                  fp16* __restrict__ H, fp16* __restrict__ L) {
    size_t i = ((size_t)blockIdx.x * 256 + threadIdx.x) * 4;
    int j = (int)(i % SEQ);
    float4 v = *(const float4*)(VT + i);
    float4 r = *(const float4*)(rinv + j);
    float f[4] = {v.x * r.x, v.y * r.y, v.z * r.z, v.w * r.w};
#pragma unroll
    for (int q = 0; q < 4; q++) {
        fp16 h = __float2half(f[q]);
        H[i + q] = h;
        L[i + q] = __float2half(f[q] - __half2float(h));
    }
}

// ---------------- launch ----------------
extern "C" void kernel_launch(void* const* d_in, const int* in_sizes, int n_in,
                              void* d_out, int out_size) {
    const float* query = (const float*)d_in[0];
    const float* key   = (const float*)d_in[1];
    const float* value = (const float*)d_in[2];
    const float* Wq    = (const float*)d_in[3];
    const float* bq    = (const float*)d_in[4];
    const float* Wk    = (const float*)d_in[5];
    const float* bk    = (const float*)d_in[6];
    const float* Wv    = (const float*)d_in[7];
    const float* bv    = (const float*)d_in[8];
    float* out = (float*)d_out;

    fp16 *xqh,*xkh,*xvh,*xvl,*WqTh,*WkTh,*WvTh,*WvTl,*Qh,*Kh,*VTh,*VTl,*Eh,*El;
    float *VTf,*rinv;
    cudaGetSymbolAddress((void**)&xqh, g_xqh);
    cudaGetSymbolAddress((void**)&xkh, g_xkh);
    cudaGetSymbolAddress((void**)&xvh, g_xvh);   cudaGetSymbolAddress((void**)&xvl, g_xvl);
    cudaGetSymbolAddress((void**)&WqTh, g_WqTh);
    cudaGetSymbolAddress((void**)&WkTh, g_WkTh);
    cudaGetSymbolAddress((void**)&WvTh, g_WvTh); cudaGetSymbolAddress((void**)&WvTl, g_WvTl);
    cudaGetSymbolAddress((void**)&Qh, g_Qh);
    cudaGetSymbolAddress((void**)&Kh, g_Kh);
    cudaGetSymbolAddress((void**)&VTf, g_VTf);
    cudaGetSymbolAddress((void**)&VTh, g_VTh);   cudaGetSymbolAddress((void**)&VTl, g_VTl);
    cudaGetSymbolAddress((void**)&Eh, g_Eh);     cudaGetSymbolAddress((void**)&El, g_El);
    cudaGetSymbolAddress((void**)&rinv, g_rinv);

    cudaFuncSetAttribute(gemm_mma<1024,0>, cudaFuncAttributeMaxDynamicSharedMemorySize, SMEM_DYN);
    cudaFuncSetAttribute(gemm_mma<1024,1>, cudaFuncAttributeMaxDynamicSharedMemorySize, SMEM_DYN);
    cudaFuncSetAttribute(gemm_mma<1024,2>, cudaFuncAttributeMaxDynamicSharedMemorySize, SMEM_DYN);
    cudaFuncSetAttribute(gemm_mma<4096,3>, cudaFuncAttributeMaxDynamicSharedMemorySize, SMEM_DYN);

    // prep
    split_kernel<false><<<SEQ*DIM/1024, 256>>>(query, xqh, nullptr);
    split_kernel<false><<<SEQ*DIM/1024, 256>>>(key,   xkh, nullptr);
    split_kernel<true ><<<SEQ*DIM/1024, 256>>>(value, xvh, xvl);
    dim3 wb(32, 8), wg(DIM/32, DIM/32);
    wtrans_kernel<false><<<wg, wb>>>(Wq, WqTh, nullptr);
    wtrans_kernel<false><<<wg, wb>>>(Wk, WkTh, nullptr);
    wtrans_kernel<true ><<<wg, wb>>>(Wv, WvTh, WvTl);

    // Q,K projections: single-pass fp16 (+bias[n])
    gemm_mma<1024,0><<<dim3(DIM/128, SEQ/128), 256, SMEM_DYN>>>(
        xqh, WqTh, nullptr, nullptr, nullptr, nullptr, 1, bq, Qh, nullptr, DIM);
    gemm_mma<1024,0><<<dim3(DIM/128, SEQ/128), 256, SMEM_DYN>>>(
        xkh, WkTh, nullptr, nullptr, nullptr, nullptr, 1, bk, Kh, nullptr, DIM);

    // V^T = WvT @ value^T + bv[m]  (3-pass split, fp32 [DIM,SEQ])
    gemm_mma<1024,1><<<dim3(SEQ/128, DIM/128), 256, SMEM_DYN>>>(
        WvTh, xvh, WvTl, xvh, WvTh, xvl, 3, bv, VTf, nullptr, SEQ);

    // E = exp((Q@K^T)/1024)  (single-pass, fp16 hi/lo out)
    gemm_mma<1024,2><<<dim3(SEQ/128, SEQ/128), 256, SMEM_DYN>>>(
        Qh, Kh, nullptr, nullptr, nullptr, nullptr, 1, nullptr, Eh, El, SEQ);

    rowsum_kernel<<<SEQ, 256>>>(Eh, El, rinv);
    scalesplit_kernel<<<(int)((size_t)DIM*SEQ/1024), 256>>>(VTf, rinv, VTh, VTl);

    // out = (E @ V'') / 4096  (3-pass split, fp32 out)
    gemm_mma<4096,3><<<dim3(DIM/128, SEQ/128), 256, SMEM_DYN>>>(
        Eh, VTh, El, VTh, Eh, VTl, 3, nullptr, out, nullptr, DIM);
}

// round 6
// speedup vs baseline: 3.9241x; 1.7746x over previous
#include <cuda_runtime.h>
#include <cuda_fp16.h>
#include <cstdint>

#define SEQ 4096
#define DIM 1024
typedef __half fp16;

// ---------------- scratch (__device__ globals; allocation-free) ----------------
__device__ __align__(256) fp16 g_xqh[SEQ*DIM];
__device__ __align__(256) fp16 g_xkh[SEQ*DIM];
__device__ __align__(256) fp16 g_xvh[SEQ*DIM], g_xvl[SEQ*DIM];
__device__ __align__(256) fp16 g_WqTh[DIM*DIM];
__device__ __align__(256) fp16 g_WkTh[DIM*DIM];
__device__ __align__(256) fp16 g_WvTh[DIM*DIM], g_WvTl[DIM*DIM];
__device__ __align__(256) fp16 g_Qh[SEQ*DIM];
__device__ __align__(256) fp16 g_Kh[SEQ*DIM];
__device__ __align__(256) float g_VTf[(size_t)DIM*SEQ];
__device__ __align__(256) fp16 g_VTh[(size_t)DIM*SEQ];
__device__ __align__(256) fp16 g_F[(size_t)SEQ*SEQ];     // F = exp(s/1024) - 1
__device__ float g_rinv[SEQ];
__device__ float g_colsum[DIM];

// ---------------- helpers ----------------
__device__ __forceinline__ uint32_t smem_u32(const void* p) {
    uint32_t a;
    asm("{ .reg .u64 t; cvta.to.shared.u64 t, %1; cvt.u32.u64 %0, t; }" : "=r"(a) : "l"(p));
    return a;
}
__device__ __forceinline__ void cp16(uint32_t s, const void* g) {
    asm volatile("cp.async.cg.shared.global [%0], [%1], 16;" :: "r"(s), "l"(g) : "memory");
}
#define CP_COMMIT() asm volatile("cp.async.commit_group;" ::: "memory")
#define CP_WAIT1()  asm volatile("cp.async.wait_group 1;" ::: "memory")
#define CP_WAIT0()  asm volatile("cp.async.wait_group 0;" ::: "memory")

__device__ __forceinline__ void mma_f16(float* c, const uint32_t* a, const uint32_t* b) {
    asm volatile(
        "mma.sync.aligned.m16n8k16.row.col.f32.f16.f16.f32 "
        "{%0,%1,%2,%3}, {%4,%5,%6,%7}, {%8,%9}, {%0,%1,%2,%3};"
        : "+f"(c[0]), "+f"(c[1]), "+f"(c[2]), "+f"(c[3])
        : "r"(a[0]), "r"(a[1]), "r"(a[2]), "r"(a[3]), "r"(b[0]), "r"(b[1]));
}
__device__ __forceinline__ void ldsm_x4(uint32_t* r, uint32_t addr) {
    asm volatile("ldmatrix.sync.aligned.m8n8.x4.shared.b16 {%0,%1,%2,%3}, [%4];"
        : "=r"(r[0]), "=r"(r[1]), "=r"(r[2]), "=r"(r[3]) : "r"(addr));
}
__device__ __forceinline__ void ldsm_x2(uint32_t* r, uint32_t addr) {
    asm volatile("ldmatrix.sync.aligned.m8n8.x2.shared.b16 {%0,%1}, [%2];"
        : "=r"(r[0]), "=r"(r[1]) : "r"(addr));
}

// ---------------------------------------------------------------------------
// fp16 HMMA GEMM: D[M,N] = sum_p A_p[M,KP] @ B_p[N,KP]^T  (fp32 accum)
// Block 128x128, BK=64, 256 thr (8 warps 2x4), 2-stage cp.async, ldmatrix.
// MODE 0: fp16 = acc + bias[n]                  (Q/K proj)
// MODE 1: f32  = acc + bias[m]                  (V^T proj)
// MODE 2: fp16 = expm1(acc/1024)                (F)
// MODE 3: f32  = acc/4096 + bias[n]             (out; bias = colsum term)
// ---------------------------------------------------------------------------
#define STRIDE 144
#define STAGE_BYTES (256 * STRIDE)
#define SMEM_DYN (2 * STAGE_BYTES)

template <int KP, int MODE>
__global__ void __launch_bounds__(256, 2)
gemm_mma(const fp16* __restrict__ A0, const fp16* __restrict__ B0,
         const fp16* __restrict__ A1, const fp16* __restrict__ B1,
         const fp16* __restrict__ A2, const fp16* __restrict__ B2,
         int npass, const float* __restrict__ bias,
         void* __restrict__ Cp0, int ldc)
{
    extern __shared__ char smem[];
    const uint32_t sb = smem_u32(smem);
    const int tid = threadIdx.x;
    const int warp = tid >> 5, lane = tid & 31;
    const int wm = warp & 1;          // 0..1 (64-row slabs)
    const int wn = warp >> 1;         // 0..3 (32-col slabs)
    const size_t bm = (size_t)blockIdx.y * 128, bn = (size_t)blockIdx.x * 128;

    constexpr int KST = KP / 64;
    const int ktot = npass * KST;

    const int lr = tid >> 1;
    const int lc = (tid & 1) * 64;

    auto load_stage = [&](int buf, int kt) {
        int p = kt / KST, kk = kt - p * KST;
        const fp16* A = (p == 0) ? A0 : (p == 1 ? A1 : A2);
        const fp16* B = (p == 0) ? B0 : (p == 1 ? B1 : B2);
        const char* ag = (const char*)(A + (bm + lr) * KP + kk * 64) + lc;
        const char* bg = (const char*)(B + (bn + lr) * KP + kk * 64) + lc;
        uint32_t sa = sb + buf * STAGE_BYTES + lr * STRIDE + lc;
        uint32_t sbB = sa + 128 * STRIDE;
#pragma unroll
        for (int i = 0; i < 4; i++) cp16(sa  + i * 16, ag + i * 16);
#pragma unroll
        for (int i = 0; i < 4; i++) cp16(sbB + i * 16, bg + i * 16);
    };

    float acc[4][4][4];
#pragma unroll
    for (int mi = 0; mi < 4; mi++)
#pragma unroll
        for (int ni = 0; ni < 4; ni++)
#pragma unroll
            for (int q = 0; q < 4; q++) acc[mi][ni][q] = 0.0f;

    load_stage(0, 0);
    CP_COMMIT();

    const uint32_t aOff = (uint32_t)(wm * 64 + (lane & 15)) * STRIDE + ((lane >> 4) << 4);
    const uint32_t bOff = (uint32_t)(wn * 32 + (lane & 7)) * STRIDE + (((lane >> 3) & 1) << 4);

    for (int kt = 0; kt < ktot; kt++) {
        const int buf = kt & 1;
        if (kt + 1 < ktot) { load_stage((kt + 1) & 1, kt + 1); CP_COMMIT(); CP_WAIT1(); }
        else               { CP_WAIT0(); }
        __syncthreads();

        const uint32_t sA = sb + buf * STAGE_BYTES;
        const uint32_t sB = sA + 128 * STRIDE;
#pragma unroll
        for (int ks = 0; ks < 4; ks++) {
            uint32_t a[4][4], b[4][2];
#pragma unroll
            for (int mi = 0; mi < 4; mi++)
                ldsm_x4(a[mi], sA + aOff + mi * (16 * STRIDE) + ks * 32);
#pragma unroll
            for (int ni = 0; ni < 4; ni++)
                ldsm_x2(b[ni], sB + bOff + ni * (8 * STRIDE) + ks * 32);
#pragma unroll
            for (int mi = 0; mi < 4; mi++)
#pragma unroll
                for (int ni = 0; ni < 4; ni++)
                    mma_f16(acc[mi][ni], a[mi], b[ni]);
        }
        __syncthreads();
    }

    // ---- epilogue ----
    const int row0 = (int)bm + wm * 64 + (lane >> 2);
    const int col0 = (int)bn + wn * 32 + (lane & 3) * 2;
#pragma unroll
    for (int mi = 0; mi < 4; mi++) {
#pragma unroll
        for (int ni = 0; ni < 4; ni++) {
#pragma unroll
            for (int h = 0; h < 2; h++) {
                int r = row0 + mi * 16 + h * 8;
                int c = col0 + ni * 8;
                float v0 = acc[mi][ni][h * 2 + 0];
                float v1 = acc[mi][ni][h * 2 + 1];
                size_t gi = (size_t)r * ldc + c;
                if (MODE == 0) {
                    v0 += bias[c]; v1 += bias[c + 1];
                    *(__half2*)((fp16*)Cp0 + gi) =
                        __halves2half2(__float2half(v0), __float2half(v1));
                } else if (MODE == 1) {
                    float bb = bias[r];
                    *(float2*)((float*)Cp0 + gi) = make_float2(v0 + bb, v1 + bb);
                } else if (MODE == 2) {
                    v0 = expm1f(v0 * (1.0f / 1024.0f));
                    v1 = expm1f(v1 * (1.0f / 1024.0f));
                    *(__half2*)((fp16*)Cp0 + gi) =
                        __halves2half2(__float2half(v0), __float2half(v1));
                } else {
                    *(float2*)((float*)Cp0 + gi) = make_float2(
                        v0 * (1.0f / 4096.0f) + bias[c],
                        v1 * (1.0f / 4096.0f) + bias[c + 1]);
                }
            }
        }
    }
}

// ---------------- prep / elementwise ----------------
template <bool LO>
__global__ void split_kernel(const float* __restrict__ X, fp16* __restrict__ H,
                             fp16* __restrict__ L) {
    size_t i = ((size_t)blockIdx.x * 256 + threadIdx.x) * 4;
    float4 v = *(const float4*)(X + i);
    float f[4] = {v.x, v.y, v.z, v.w};
#pragma unroll
    for (int j = 0; j < 4; j++) {
        fp16 h = __float2half(f[j]);
        H[i + j] = h;
        if (LO) L[i + j] = __float2half(f[j] - __half2float(h));
    }
}

template <bool LO>
__global__ void wtrans_kernel(const float* __restrict__ W, fp16* __restrict__ TH,
                              fp16* __restrict__ TL) {
    __shared__ float t[32][33];
    int k0 = blockIdx.y * 32, n0 = blockIdx.x * 32;
    int tx = threadIdx.x, ty = threadIdx.y;
    for (int r = ty; r < 32; r += 8) t[r][tx] = W[(size_t)(k0 + r) * DIM + n0 + tx];
    __syncthreads();
    for (int r = ty; r < 32; r += 8) {
        float v = t[tx][r];
        size_t gi = (size_t)(n0 + r) * DIM + (k0 + tx);
        fp16 h = __float2half(v);
        TH[gi] = h;
        if (LO) TL[gi] = __float2half(v - __half2float(h));
    }
}

__device__ __forceinline__ float sum2h(uint32_t u) {
    __half2 b = *reinterpret_cast<__half2*>(&u);
    float2 f = __half22float2(b);
    return f.x + f.y;
}
// r[row] = 4096 + sum_j F[row][j];  rinv = 4096 / r
__global__ void rowsum_kernel(const fp16* __restrict__ F, float* __restrict__ rinv) {
    int row = blockIdx.x;
    const uint4* ph = (const uint4*)(F + (size_t)row * SEQ);
    float s = 0.f;
    for (int i = threadIdx.x; i < SEQ / 8; i += 256) {
        uint4 a = ph[i];
        s += sum2h(a.x) + sum2h(a.y) + sum2h(a.z) + sum2h(a.w);
    }
    __shared__ float sm[8];
#pragma unroll
    for (int o = 16; o > 0; o >>= 1) s += __shfl_down_sync(0xFFFFFFFFu, s, o);
    if ((threadIdx.x & 31) == 0) sm[threadIdx.x >> 5] = s;
    __syncthreads();
    if (threadIdx.x < 8) {
        s = sm[threadIdx.x];
#pragma unroll
        for (int o = 4; o > 0; o >>= 1) s += __shfl_down_sync(0xFFu, s, o);
        if (threadIdx.x == 0) rinv[row] = 4096.0f / (4096.0f + s);
    }
}

// V''T[d][j] = VT[d][j] * rinv[j]  (fp16, x4096-normalized via rinv)
__global__ void scale_kernel(const float* __restrict__ VT,
                             const float* __restrict__ rinv,
                             fp16* __restrict__ H) {
    size_t i = ((size_t)blockIdx.x * 256 + threadIdx.x) * 4;
    int j = (int)(i % SEQ);
    float4 v = *(const float4*)(VT + i);
    float4 r = *(const float4*)(rinv + j);
    *(__half2*)(H + i)     = __halves2half2(__float2half(v.x * r.x), __float2half(v.y * r.y));
    *(__half2*)(H + i + 2) = __halves2half2(__float2half(v.z * r.z), __float2half(v.w * r.w));
}

// colsum[d] = (1/4096) * sum_j VT[d][j] * rinv[j]   ( = sum_j V'[j][d] )
__global__ void colsum_kernel(const float* __restrict__ VT,
                              const float* __restrict__ rinv,
                              float* __restrict__ cs) {
    int d = blockIdx.x;
    const float4* pv = (const float4*)(VT + (size_t)d * SEQ);
    const float4* pr = (const float4*)rinv;
    float s = 0.f;
    for (int i = threadIdx.x; i < SEQ / 4; i += 256) {
        float4 v = pv[i], r = pr[i];
        s += v.x * r.x + v.y * r.y + v.z * r.z + v.w * r.w;
    }
    __shared__ float sm[8];
#pragma unroll
    for (int o = 16; o > 0; o >>= 1) s += __shfl_down_sync(0xFFFFFFFFu, s, o);
    if ((threadIdx.x & 31) == 0) sm[threadIdx.x >> 5] = s;
    __syncthreads();
    if (threadIdx.x < 8) {
        s = sm[threadIdx.x];
#pragma unroll
        for (int o = 4; o > 0; o >>= 1) s += __shfl_down_sync(0xFFu, s, o);
        if (threadIdx.x == 0) cs[d] = s * (1.0f / 4096.0f);
    }
}

// ---------------- launch ----------------
extern "C" void kernel_launch(void* const* d_in, const int* in_sizes, int n_in,
                              void* d_out, int out_size) {
    const float* query = (const float*)d_in[0];
    const float* key   = (const float*)d_in[1];
    const float* value = (const float*)d_in[2];
    const float* Wq    = (const float*)d_in[3];
    const float* bq    = (const float*)d_in[4];
    const float* Wk    = (const float*)d_in[5];
    const float* bk    = (const float*)d_in[6];
    const float* Wv    = (const float*)d_in[7];
    const float* bv    = (const float*)d_in[8];
    float* out = (float*)d_out;

    fp16 *xqh,*xkh,*xvh,*xvl,*WqTh,*WkTh,*WvTh,*WvTl,*Qh,*Kh,*VTh,*F;
    float *VTf,*rinv,*cs;
    cudaGetSymbolAddress((void**)&xqh, g_xqh);
    cudaGetSymbolAddress((void**)&xkh, g_xkh);
    cudaGetSymbolAddress((void**)&xvh, g_xvh);   cudaGetSymbolAddress((void**)&xvl, g_xvl);
    cudaGetSymbolAddress((void**)&WqTh, g_WqTh);
    cudaGetSymbolAddress((void**)&WkTh, g_WkTh);
    cudaGetSymbolAddress((void**)&WvTh, g_WvTh); cudaGetSymbolAddress((void**)&WvTl, g_WvTl);
    cudaGetSymbolAddress((void**)&Qh, g_Qh);
    cudaGetSymbolAddress((void**)&Kh, g_Kh);
    cudaGetSymbolAddress((void**)&VTf, g_VTf);
    cudaGetSymbolAddress((void**)&VTh, g_VTh);
    cudaGetSymbolAddress((void**)&F, g_F);
    cudaGetSymbolAddress((void**)&rinv, g_rinv);
    cudaGetSymbolAddress((void**)&cs, g_colsum);

    cudaFuncSetAttribute(gemm_mma<1024,0>, cudaFuncAttributeMaxDynamicSharedMemorySize, SMEM_DYN);
    cudaFuncSetAttribute(gemm_mma<1024,1>, cudaFuncAttributeMaxDynamicSharedMemorySize, SMEM_DYN);
    cudaFuncSetAttribute(gemm_mma<1024,2>, cudaFuncAttributeMaxDynamicSharedMemorySize, SMEM_DYN);
    cudaFuncSetAttribute(gemm_mma<4096,3>, cudaFuncAttributeMaxDynamicSharedMemorySize, SMEM_DYN);

    // prep
    split_kernel<false><<<SEQ*DIM/1024, 256>>>(query, xqh, nullptr);
    split_kernel<false><<<SEQ*DIM/1024, 256>>>(key,   xkh, nullptr);
    split_kernel<true ><<<SEQ*DIM/1024, 256>>>(value, xvh, xvl);
    dim3 wb(32, 8), wg(DIM/32, DIM/32);
    wtrans_kernel<false><<<wg, wb>>>(Wq, WqTh, nullptr);
    wtrans_kernel<false><<<wg, wb>>>(Wk, WkTh, nullptr);
    wtrans_kernel<true ><<<wg, wb>>>(Wv, WvTh, WvTl);

    // Q,K projections: single-pass fp16 (+bias[n])
    gemm_mma<1024,0><<<dim3(DIM/128, SEQ/128), 256, SMEM_DYN>>>(
        xqh, WqTh, nullptr, nullptr, nullptr, nullptr, 1, bq, Qh, DIM);
    gemm_mma<1024,0><<<dim3(DIM/128, SEQ/128), 256, SMEM_DYN>>>(
        xkh, WkTh, nullptr, nullptr, nullptr, nullptr, 1, bk, Kh, DIM);

    // V^T = WvT @ value^T + bv[m]  (3-pass split, fp32 [DIM,SEQ])
    gemm_mma<1024,1><<<dim3(SEQ/128, DIM/128), 256, SMEM_DYN>>>(
        WvTh, xvh, WvTl, xvh, WvTh, xvl, 3, bv, VTf, SEQ);

    // F = expm1((Q@K^T)/1024)   (single-pass, fp16)
    gemm_mma<1024,2><<<dim3(SEQ/128, SEQ/128), 256, SMEM_DYN>>>(
        Qh, Kh, nullptr, nullptr, nullptr, nullptr, 1, nullptr, F, SEQ);

    rowsum_kernel<<<SEQ, 256>>>(F, rinv);
    scale_kernel<<<(int)((size_t)DIM*SEQ/1024), 256>>>(VTf, rinv, VTh);
    colsum_kernel<<<DIM, 256>>>(VTf, rinv, cs);

    // out = F @ V'' / 4096 + colsum   (single-pass)
    gemm_mma<4096,3><<<dim3(DIM/128, SEQ/128), 256, SMEM_DYN>>>(
        F, VTh, nullptr, nullptr, nullptr, nullptr, 1, cs, out, DIM);
}

// round 7
// speedup vs baseline: 5.3205x; 1.3559x over previous
#include <cuda_runtime.h>
#include <cuda_fp16.h>
#include <cstdint>

#define SEQ 4096
#define DIM 1024
typedef __half fp16;

// ---------------- scratch ----------------
__device__ __align__(256) fp16 g_xqh[SEQ*DIM];
__device__ __align__(256) fp16 g_xkh[SEQ*DIM];
__device__ __align__(256) fp16 g_xvh[SEQ*DIM], g_xvl[SEQ*DIM];
__device__ __align__(256) fp16 g_WqTh[DIM*DIM];
__device__ __align__(256) fp16 g_WkTh[DIM*DIM];
__device__ __align__(256) fp16 g_WvTh[DIM*DIM], g_WvTl[DIM*DIM];
__device__ __align__(256) fp16 g_Qh[SEQ*DIM];
__device__ __align__(256) fp16 g_Kh[SEQ*DIM];
__device__ __align__(256) float g_VTf[(size_t)DIM*SEQ];
__device__ __align__(256) fp16 g_VTh[(size_t)DIM*SEQ];
__device__ __align__(256) fp16 g_F[(size_t)SEQ*SEQ];
__device__ float g_r[SEQ];          // rowsum of F (atomic accum)
__device__ float g_colsum[DIM];

// ---------------- helpers ----------------
__device__ __forceinline__ uint32_t smem_u32(const void* p) {
    uint32_t a;
    asm("{ .reg .u64 t; cvta.to.shared.u64 t, %1; cvt.u32.u64 %0, t; }" : "=r"(a) : "l"(p));
    return a;
}
__device__ __forceinline__ void cp16(uint32_t s, const void* g) {
    asm volatile("cp.async.cg.shared.global [%0], [%1], 16;" :: "r"(s), "l"(g) : "memory");
}
#define CP_COMMIT() asm volatile("cp.async.commit_group;" ::: "memory")
#define CP_WAIT2()  asm volatile("cp.async.wait_group 2;" ::: "memory")
#define CP_WAIT1()  asm volatile("cp.async.wait_group 1;" ::: "memory")
#define CP_WAIT0()  asm volatile("cp.async.wait_group 0;" ::: "memory")

__device__ __forceinline__ void mma_f16(float* c, const uint32_t* a, const uint32_t* b) {
    asm volatile(
        "mma.sync.aligned.m16n8k16.row.col.f32.f16.f16.f32 "
        "{%0,%1,%2,%3}, {%4,%5,%6,%7}, {%8,%9}, {%0,%1,%2,%3};"
        : "+f"(c[0]), "+f"(c[1]), "+f"(c[2]), "+f"(c[3])
        : "r"(a[0]), "r"(a[1]), "r"(a[2]), "r"(a[3]), "r"(b[0]), "r"(b[1]));
}
__device__ __forceinline__ void ldsm_x4(uint32_t* r, uint32_t addr) {
    asm volatile("ldmatrix.sync.aligned.m8n8.x4.shared.b16 {%0,%1,%2,%3}, [%4];"
        : "=r"(r[0]), "=r"(r[1]), "=r"(r[2]), "=r"(r[3]) : "r"(addr));
}

// ---------------------------------------------------------------------------
// fp16 HMMA GEMM: D[M,N] = sum_p A_p[M,KP] @ B_p[N,KP]^T  (fp32 accum)
// Block 128x256, BK=64, 256 thr (8 warps 2x4, 64x64 warp tile), 3-stage.
// MODE 0: fp16 = acc + bias[n]         MODE 1: f32 = acc + bias[m]
// MODE 2: fp16 = expm1(acc/1024), rowsum atomics -> Rp
// MODE 3: f32  = acc/4096 + bias[n]
// ---------------------------------------------------------------------------
#define STRIDE 144
#define STAGE_BYTES (384 * STRIDE)           // 55296
#define SMEM_DYN (3 * STAGE_BYTES)           // 165888

template <int KP, int MODE>
__global__ void __launch_bounds__(256, 1)
gemm_mma(const fp16* __restrict__ A0, const fp16* __restrict__ B0,
         const fp16* __restrict__ A1, const fp16* __restrict__ B1,
         const fp16* __restrict__ A2, const fp16* __restrict__ B2,
         int npass, const float* __restrict__ bias, float* __restrict__ Rp,
         void* __restrict__ Cp0, int ldc)
{
    extern __shared__ char smem[];
    const uint32_t sb = smem_u32(smem);
    const int tid = threadIdx.x;
    const int warp = tid >> 5, lane = tid & 31;
    const int wm = warp & 1;          // 0..1 (64-row slabs)
    const int wn = warp >> 1;         // 0..3 (64-col slabs)
    const size_t bm = (size_t)blockIdx.y * 128, bn = (size_t)blockIdx.x * 256;

    constexpr int KST = KP / 64;
    const int ktot = npass * KST;

    const int lrow = tid >> 3;          // 0..31 within 32-row group
    const int lch  = (tid & 7) * 16;    // byte chunk within 128B row

    auto load_stage = [&](int buf, int kt) {
        int p = kt / KST, kk = kt - p * KST;
        const fp16* A = (p == 0) ? A0 : (p == 1 ? A1 : A2);
        const fp16* B = (p == 0) ? B0 : (p == 1 ? B1 : B2);
        const char* ag = (const char*)(A + (bm + lrow) * KP) + kk * 128 + lch;
        const char* bg = (const char*)(B + (bn + lrow) * KP) + kk * 128 + lch;
        uint32_t sa  = sb + buf * STAGE_BYTES + lrow * STRIDE + lch;
        uint32_t sbB = sa + 128 * STRIDE;
#pragma unroll
        for (int i = 0; i < 4; i++)     // A: 128 rows
            cp16(sa + i * (32 * STRIDE), ag + (size_t)i * (32 * KP * 2));
#pragma unroll
        for (int i = 0; i < 8; i++)     // B: 256 rows
            cp16(sbB + i * (32 * STRIDE), bg + (size_t)i * (32 * KP * 2));
    };

    float acc[4][8][4];
#pragma unroll
    for (int mi = 0; mi < 4; mi++)
#pragma unroll
        for (int nj = 0; nj < 8; nj++)
#pragma unroll
            for (int q = 0; q < 4; q++) acc[mi][nj][q] = 0.0f;

    load_stage(0, 0); CP_COMMIT();
    load_stage(1, 1); CP_COMMIT();

    // ldmatrix lane offsets
    const uint32_t aOff = (uint32_t)(wm * 64 + (lane & 15)) * STRIDE + ((lane >> 4) << 4);
    const uint32_t bOff = (uint32_t)(wn * 64 + (lane & 7) + ((lane >> 4) & 1) * 8) * STRIDE
                          + (((lane >> 3) & 1) << 4);

    int buf = 0;
    for (int kt = 0; kt < ktot; kt++) {
        if (kt + 2 < ktot) {
            load_stage((buf + 2) % 3, kt + 2); CP_COMMIT(); CP_WAIT2();
        } else if (kt + 1 < ktot) { CP_WAIT1(); }
        else                      { CP_WAIT0(); }
        __syncthreads();

        const uint32_t sA = sb + buf * STAGE_BYTES;
        const uint32_t sB = sA + 128 * STRIDE;
#pragma unroll
        for (int ks = 0; ks < 4; ks++) {
            uint32_t a[4][4], b[4][4];
#pragma unroll
            for (int mi = 0; mi < 4; mi++)
                ldsm_x4(a[mi], sA + aOff + mi * (16 * STRIDE) + ks * 32);
#pragma unroll
            for (int ni = 0; ni < 4; ni++)
                ldsm_x4(b[ni], sB + bOff + ni * (16 * STRIDE) + ks * 32);
#pragma unroll
            for (int mi = 0; mi < 4; mi++)
#pragma unroll
                for (int ni = 0; ni < 4; ni++) {
                    mma_f16(acc[mi][ni * 2],     a[mi], &b[ni][0]);
                    mma_f16(acc[mi][ni * 2 + 1], a[mi], &b[ni][2]);
                }
        }
        __syncthreads();
        buf = (buf + 1) % 3;
    }

    // ---- epilogue ----
    const int row0 = (int)bm + wm * 64 + (lane >> 2);
    const int col0 = (int)bn + wn * 64 + (lane & 3) * 2;
#pragma unroll
    for (int mi = 0; mi < 4; mi++) {
#pragma unroll
        for (int h = 0; h < 2; h++) {
            const int r = row0 + mi * 16 + h * 8;
            float rs = 0.0f;
#pragma unroll
            for (int nj = 0; nj < 8; nj++) {
                const int c = col0 + nj * 8;
                float v0 = acc[mi][nj][h * 2 + 0];
                float v1 = acc[mi][nj][h * 2 + 1];
                size_t gi = (size_t)r * ldc + c;
                if (MODE == 0) {
                    v0 += bias[c]; v1 += bias[c + 1];
                    *(__half2*)((fp16*)Cp0 + gi) =
                        __halves2half2(__float2half(v0), __float2half(v1));
                } else if (MODE == 1) {
                    float bb = bias[r];
                    *(float2*)((float*)Cp0 + gi) = make_float2(v0 + bb, v1 + bb);
                } else if (MODE == 2) {
                    v0 = expm1f(v0 * (1.0f / 1024.0f));
                    v1 = expm1f(v1 * (1.0f / 1024.0f));
                    *(__half2*)((fp16*)Cp0 + gi) =
                        __halves2half2(__float2half(v0), __float2half(v1));
                    rs += v0 + v1;
                } else {
                    *(float2*)((float*)Cp0 + gi) = make_float2(
                        v0 * (1.0f / 4096.0f) + bias[c],
                        v1 * (1.0f / 4096.0f) + bias[c + 1]);
                }
            }
            if (MODE == 2) {
                rs += __shfl_xor_sync(0xFFFFFFFFu, rs, 1);
                rs += __shfl_xor_sync(0xFFFFFFFFu, rs, 2);
                if ((lane & 3) == 0) atomicAdd(Rp + r, rs);
            }
        }
    }
}

// ---------------- prep: inputs -> fp16 (value also lo split); zero g_r ----------------
__global__ void prep_inputs(const float* __restrict__ q, const float* __restrict__ k,
                            const float* __restrict__ v,
                            fp16* __restrict__ qh, fp16* __restrict__ kh,
                            fp16* __restrict__ vh, fp16* __restrict__ vl,
                            float* __restrict__ r) {
    size_t i = ((size_t)blockIdx.x * 256 + threadIdx.x) * 4;
    const float* X = (blockIdx.y == 0) ? q : (blockIdx.y == 1) ? k : v;
    float4 val = *(const float4*)(X + i);
    float f[4] = {val.x, val.y, val.z, val.w};
    fp16* H = (blockIdx.y == 0) ? qh : (blockIdx.y == 1) ? kh : vh;
#pragma unroll
    for (int j = 0; j < 4; j++) {
        fp16 h = __float2half(f[j]);
        H[i + j] = h;
        if (blockIdx.y == 2) vl[i + j] = __float2half(f[j] - __half2float(h));
    }
    if (blockIdx.y == 0 && blockIdx.x < SEQ / 1024)
        *(float4*)(r + blockIdx.x * 1024 + threadIdx.x * 4) = make_float4(0.f, 0.f, 0.f, 0.f);
}

// ---------------- prep: W -> W^T fp16 (Wv also lo) ----------------
__global__ void prep_weights(const float* __restrict__ Wq, const float* __restrict__ Wk,
                             const float* __restrict__ Wv,
                             fp16* __restrict__ TQ, fp16* __restrict__ TK,
                             fp16* __restrict__ TVh, fp16* __restrict__ TVl) {
    __shared__ float t[32][33];
    const float* W = (blockIdx.z == 0) ? Wq : (blockIdx.z == 1) ? Wk : Wv;
    int k0 = blockIdx.y * 32, n0 = blockIdx.x * 32;
    int tx = threadIdx.x, ty = threadIdx.y;
    for (int r = ty; r < 32; r += 8) t[r][tx] = W[(size_t)(k0 + r) * DIM + n0 + tx];
    __syncthreads();
    fp16* TH = (blockIdx.z == 0) ? TQ : (blockIdx.z == 1) ? TK : TVh;
    for (int r = ty; r < 32; r += 8) {
        float v = t[tx][r];
        size_t gi = (size_t)(n0 + r) * DIM + (k0 + tx);
        fp16 h = __float2half(v);
        TH[gi] = h;
        if (blockIdx.z == 2) TVl[gi] = __float2half(v - __half2float(h));
    }
}

// ---------------- fused scale + colsum ----------------
// V''T[d][j] = VTf[d][j] * 4096/(4096+r[j])  -> fp16
// cs[d] = sum_j V''T[d][j] / 4096
__global__ void scale_colsum(const float* __restrict__ VT, const float* __restrict__ r,
                             fp16* __restrict__ H, float* __restrict__ cs) {
    int d = blockIdx.x;
    const float4* pv = (const float4*)(VT + (size_t)d * SEQ);
    const float4* pr = (const float4*)r;
    fp16* ph = H + (size_t)d * SEQ;
    float s = 0.f;
    for (int i = threadIdx.x; i < SEQ / 4; i += 256) {
        float4 v = pv[i], rr = pr[i];
        float f0 = v.x * (4096.0f / (4096.0f + rr.x));
        float f1 = v.y * (4096.0f / (4096.0f + rr.y));
        float f2 = v.z * (4096.0f / (4096.0f + rr.z));
        float f3 = v.w * (4096.0f / (4096.0f + rr.w));
        *(__half2*)(ph + i * 4)     = __halves2half2(__float2half(f0), __float2half(f1));
        *(__half2*)(ph + i * 4 + 2) = __halves2half2(__float2half(f2), __float2half(f3));
        s += (f0 + f1) + (f2 + f3);
    }
    __shared__ float sm[8];
#pragma unroll
    for (int o = 16; o > 0; o >>= 1) s += __shfl_down_sync(0xFFFFFFFFu, s, o);
    if ((threadIdx.x & 31) == 0) sm[threadIdx.x >> 5] = s;
    __syncthreads();
    if (threadIdx.x < 8) {
        s = sm[threadIdx.x];
#pragma unroll
        for (int o = 4; o > 0; o >>= 1) s += __shfl_down_sync(0xFFu, s, o);
        if (threadIdx.x == 0) cs[d] = s * (1.0f / 4096.0f);
    }
}

// ---------------- launch ----------------
extern "C" void kernel_launch(void* const* d_in, const int* in_sizes, int n_in,
                              void* d_out, int out_size) {
    const float* query = (const float*)d_in[0];
    const float* key   = (const float*)d_in[1];
    const float* value = (const float*)d_in[2];
    const float* Wq    = (const float*)d_in[3];
    const float* bq    = (const float*)d_in[4];
    const float* Wk    = (const float*)d_in[5];
    const float* bk    = (const float*)d_in[6];
    const float* Wv    = (const float*)d_in[7];
    const float* bv    = (const float*)d_in[8];
    float* out = (float*)d_out;

    fp16 *xqh,*xkh,*xvh,*xvl,*WqTh,*WkTh,*WvTh,*WvTl,*Qh,*Kh,*VTh,*F;
    float *VTf,*r,*cs;
    cudaGetSymbolAddress((void**)&xqh, g_xqh);
    cudaGetSymbolAddress((void**)&xkh, g_xkh);
    cudaGetSymbolAddress((void**)&xvh, g_xvh);   cudaGetSymbolAddress((void**)&xvl, g_xvl);
    cudaGetSymbolAddress((void**)&WqTh, g_WqTh);
    cudaGetSymbolAddress((void**)&WkTh, g_WkTh);
    cudaGetSymbolAddress((void**)&WvTh, g_WvTh); cudaGetSymbolAddress((void**)&WvTl, g_WvTl);
    cudaGetSymbolAddress((void**)&Qh, g_Qh);
    cudaGetSymbolAddress((void**)&Kh, g_Kh);
    cudaGetSymbolAddress((void**)&VTf, g_VTf);
    cudaGetSymbolAddress((void**)&VTh, g_VTh);
    cudaGetSymbolAddress((void**)&F, g_F);
    cudaGetSymbolAddress((void**)&r, g_r);
    cudaGetSymbolAddress((void**)&cs, g_colsum);

    cudaFuncSetAttribute(gemm_mma<1024,0>, cudaFuncAttributeMaxDynamicSharedMemorySize, SMEM_DYN);
    cudaFuncSetAttribute(gemm_mma<1024,1>, cudaFuncAttributeMaxDynamicSharedMemorySize, SMEM_DYN);
    cudaFuncSetAttribute(gemm_mma<1024,2>, cudaFuncAttributeMaxDynamicSharedMemorySize, SMEM_DYN);
    cudaFuncSetAttribute(gemm_mma<4096,3>, cudaFuncAttributeMaxDynamicSharedMemorySize, SMEM_DYN);

    // (0) inputs -> fp16 (+ zero rowsum accumulator)
    prep_inputs<<<dim3(SEQ*DIM/1024, 3), 256>>>(query, key, value, xqh, xkh, xvh, xvl, r);
    // (1) weights -> W^T fp16
    prep_weights<<<dim3(DIM/32, DIM/32, 3), dim3(32, 8)>>>(Wq, Wk, Wv, WqTh, WkTh, WvTh, WvTl);

    // (2,3) Q,K projections: single-pass fp16 (+bias[n])
    gemm_mma<1024,0><<<dim3(DIM/256, SEQ/128), 256, SMEM_DYN>>>(
        xqh, WqTh, nullptr, nullptr, nullptr, nullptr, 1, bq, nullptr, Qh, DIM);
    gemm_mma<1024,0><<<dim3(DIM/256, SEQ/128), 256, SMEM_DYN>>>(
        xkh, WkTh, nullptr, nullptr, nullptr, nullptr, 1, bk, nullptr, Kh, DIM);

    // (4) V^T = WvT @ value^T + bv[m]  (3-pass split, fp32 [DIM,SEQ])
    gemm_mma<1024,1><<<dim3(SEQ/256, DIM/128), 256, SMEM_DYN>>>(
        WvTh, xvh, WvTl, xvh, WvTh, xvl, 3, bv, nullptr, VTf, SEQ);

    // (5) F = expm1((Q@K^T)/1024), fused rowsum  <- ncu -s 5 profiles this
    gemm_mma<1024,2><<<dim3(SEQ/256, SEQ/128), 256, SMEM_DYN>>>(
        Qh, Kh, nullptr, nullptr, nullptr, nullptr, 1, nullptr, r, F, SEQ);

    // (6) V'' scale + colsum
    scale_colsum<<<DIM, 256>>>(VTf, r, VTh, cs);

    // (7) out = F @ V'' / 4096 + colsum
    gemm_mma<4096,3><<<dim3(DIM/256, SEQ/128), 256, SMEM_DYN>>>(
        F, VTh, nullptr, nullptr, nullptr, nullptr, 1, cs, nullptr, out, DIM);
}

// round 8
// speedup vs baseline: 5.5317x; 1.0397x over previous
#include <cuda_runtime.h>
#include <cuda_fp16.h>
#include <cstdint>

#define SEQ 4096
#define DIM 1024
typedef __half fp16;

// ---------------- scratch ----------------
__device__ __align__(256) fp16 g_xqh[SEQ*DIM];
__device__ __align__(256) fp16 g_xkh[SEQ*DIM];
__device__ __align__(256) fp16 g_xvh[SEQ*DIM];
__device__ __align__(256) fp16 g_WqTh[DIM*DIM];
__device__ __align__(256) fp16 g_WkTh[DIM*DIM];
__device__ __align__(256) fp16 g_WvTh[DIM*DIM];
__device__ __align__(256) fp16 g_Qh[SEQ*DIM];
__device__ __align__(256) fp16 g_Kh[SEQ*DIM];
__device__ __align__(256) fp16 g_VTh[(size_t)DIM*SEQ];   // V^T + bv, fp16
__device__ __align__(256) fp16 g_VTs[(size_t)DIM*SEQ];   // V''^T scaled
__device__ __align__(256) fp16 g_F[(size_t)SEQ*SEQ];
__device__ float g_r[SEQ];          // rowsum of F (atomic accum)
__device__ float g_t[DIM];          // t = value^T @ rinv (atomic accum)
__device__ float g_cs[DIM];         // colsum (atomic accum)
__device__ float g_s0[1];           // sum of 1/rsum

// ---------------- helpers ----------------
__device__ __forceinline__ uint32_t smem_u32(const void* p) {
    uint32_t a;
    asm("{ .reg .u64 t; cvta.to.shared.u64 t, %1; cvt.u32.u64 %0, t; }" : "=r"(a) : "l"(p));
    return a;
}
__device__ __forceinline__ void cp16(uint32_t s, const void* g) {
    asm volatile("cp.async.cg.shared.global [%0], [%1], 16;" :: "r"(s), "l"(g) : "memory");
}
#define CP_COMMIT() asm volatile("cp.async.commit_group;" ::: "memory")
#define CP_WAIT2()  asm volatile("cp.async.wait_group 2;" ::: "memory")
#define CP_WAIT1()  asm volatile("cp.async.wait_group 1;" ::: "memory")
#define CP_WAIT0()  asm volatile("cp.async.wait_group 0;" ::: "memory")

__device__ __forceinline__ void mma_f16(float* c, const uint32_t* a, const uint32_t* b) {
    asm volatile(
        "mma.sync.aligned.m16n8k16.row.col.f32.f16.f16.f32 "
        "{%0,%1,%2,%3}, {%4,%5,%6,%7}, {%8,%9}, {%0,%1,%2,%3};"
        : "+f"(c[0]), "+f"(c[1]), "+f"(c[2]), "+f"(c[3])
        : "r"(a[0]), "r"(a[1]), "r"(a[2]), "r"(a[3]), "r"(b[0]), "r"(b[1]));
}
__device__ __forceinline__ void ldsm_x4(uint32_t* r, uint32_t addr) {
    asm volatile("ldmatrix.sync.aligned.m8n8.x4.shared.b16 {%0,%1,%2,%3}, [%4];"
        : "=r"(r[0]), "=r"(r[1]), "=r"(r[2]), "=r"(r[3]) : "r"(addr));
}

// ---------------------------------------------------------------------------
// fp16 HMMA GEMM: D[M,N] = A[M,KP] @ B[N,KP]^T  (fp32 accum)
// Block 128x256, BK=64, 256 thr (8 warps 2x4, 64x64 warp tile), 3-stage,
// fragment double-buffering.
// MODE 0: fp16 = acc + bias[n]    (Q/K proj)
// MODE 4: fp16 = acc + bias[m]    (V^T proj)
// MODE 2: fp16 = expm1(acc/1024), rowsum atomics -> Rp
// MODE 3: f32  = acc/4096 + bias[n]
// ---------------------------------------------------------------------------
#define STRIDE 144
#define STAGE_BYTES (384 * STRIDE)           // 55296
#define SMEM_DYN (3 * STAGE_BYTES)           // 165888

template <int KP, int MODE>
__global__ void __launch_bounds__(256, 1)
gemm_mma(const fp16* __restrict__ A0, const fp16* __restrict__ B0,
         const float* __restrict__ bias, float* __restrict__ Rp,
         void* __restrict__ Cp0, int ldc)
{
    extern __shared__ char smem[];
    const uint32_t sb = smem_u32(smem);
    const int tid = threadIdx.x;
    const int warp = tid >> 5, lane = tid & 31;
    const int wm = warp & 1;          // 0..1 (64-row slabs)
    const int wn = warp >> 1;         // 0..3 (64-col slabs)
    const size_t bm = (size_t)blockIdx.y * 128, bn = (size_t)blockIdx.x * 256;

    const int ktot = KP / 64;

    const int lrow = tid >> 3;          // 0..31
    const int lch  = (tid & 7) * 16;    // byte chunk in 128B row

    auto load_stage = [&](int buf, int kt) {
        const char* ag = (const char*)(A0 + (bm + lrow) * KP) + kt * 128 + lch;
        const char* bg = (const char*)(B0 + (bn + lrow) * KP) + kt * 128 + lch;
        uint32_t sa  = sb + buf * STAGE_BYTES + lrow * STRIDE + lch;
        uint32_t sbB = sa + 128 * STRIDE;
#pragma unroll
        for (int i = 0; i < 4; i++)
            cp16(sa + i * (32 * STRIDE), ag + (size_t)i * (32 * KP * 2));
#pragma unroll
        for (int i = 0; i < 8; i++)
            cp16(sbB + i * (32 * STRIDE), bg + (size_t)i * (32 * KP * 2));
    };

    float acc[4][8][4];
#pragma unroll
    for (int mi = 0; mi < 4; mi++)
#pragma unroll
        for (int nj = 0; nj < 8; nj++)
#pragma unroll
            for (int q = 0; q < 4; q++) acc[mi][nj][q] = 0.0f;

    load_stage(0, 0); CP_COMMIT();
    load_stage(1, 1); CP_COMMIT();

    const uint32_t aOff = (uint32_t)(wm * 64 + (lane & 15)) * STRIDE + ((lane >> 4) << 4);
    const uint32_t bOff = (uint32_t)(wn * 64 + (lane & 7) + ((lane >> 4) & 1) * 8) * STRIDE
                          + (((lane >> 3) & 1) << 4);

    int buf = 0;
    for (int kt = 0; kt < ktot; kt++) {
        if (kt + 2 < ktot) {
            load_stage((buf + 2) % 3, kt + 2); CP_COMMIT(); CP_WAIT2();
        } else if (kt + 1 < ktot) { CP_WAIT1(); }
        else                      { CP_WAIT0(); }
        __syncthreads();

        const uint32_t sA = sb + buf * STAGE_BYTES;
        const uint32_t sB = sA + 128 * STRIDE;

        uint32_t a[2][4][4], b[2][4][4];
        // preload ks=0 fragments
#pragma unroll
        for (int mi = 0; mi < 4; mi++)
            ldsm_x4(a[0][mi], sA + aOff + mi * (16 * STRIDE));
#pragma unroll
        for (int ni = 0; ni < 4; ni++)
            ldsm_x4(b[0][ni], sB + bOff + ni * (16 * STRIDE));

#pragma unroll
        for (int ks = 0; ks < 4; ks++) {
            const int cur = ks & 1, nxt = cur ^ 1;
            if (ks < 3) {
#pragma unroll
                for (int mi = 0; mi < 4; mi++)
                    ldsm_x4(a[nxt][mi], sA + aOff + mi * (16 * STRIDE) + (ks + 1) * 32);
#pragma unroll
                for (int ni = 0; ni < 4; ni++)
                    ldsm_x4(b[nxt][ni], sB + bOff + ni * (16 * STRIDE) + (ks + 1) * 32);
            }
#pragma unroll
            for (int mi = 0; mi < 4; mi++)
#pragma unroll
                for (int ni = 0; ni < 4; ni++) {
                    mma_f16(acc[mi][ni * 2],     a[cur][mi], &b[cur][ni][0]);
                    mma_f16(acc[mi][ni * 2 + 1], a[cur][mi], &b[cur][ni][2]);
                }
        }
        __syncthreads();
        buf = (buf + 1) % 3;
    }

    // ---- epilogue ----
    const int row0 = (int)bm + wm * 64 + (lane >> 2);
    const int col0 = (int)bn + wn * 64 + (lane & 3) * 2;
#pragma unroll
    for (int mi = 0; mi < 4; mi++) {
#pragma unroll
        for (int h = 0; h < 2; h++) {
            const int r = row0 + mi * 16 + h * 8;
            float rs = 0.0f;
            float bm_b = (MODE == 4) ? bias[r] : 0.0f;
#pragma unroll
            for (int nj = 0; nj < 8; nj++) {
                const int c = col0 + nj * 8;
                float v0 = acc[mi][nj][h * 2 + 0];
                float v1 = acc[mi][nj][h * 2 + 1];
                size_t gi = (size_t)r * ldc + c;
                if (MODE == 0) {
                    v0 += bias[c]; v1 += bias[c + 1];
                    *(__half2*)((fp16*)Cp0 + gi) =
                        __halves2half2(__float2half(v0), __float2half(v1));
                } else if (MODE == 4) {
                    *(__half2*)((fp16*)Cp0 + gi) =
                        __halves2half2(__float2half(v0 + bm_b), __float2half(v1 + bm_b));
                } else if (MODE == 2) {
                    v0 = expm1f(v0 * (1.0f / 1024.0f));
                    v1 = expm1f(v1 * (1.0f / 1024.0f));
                    *(__half2*)((fp16*)Cp0 + gi) =
                        __halves2half2(__float2half(v0), __float2half(v1));
                    rs += v0 + v1;
                } else {
                    *(float2*)((float*)Cp0 + gi) = make_float2(
                        v0 * (1.0f / 4096.0f) + bias[c],
                        v1 * (1.0f / 4096.0f) + bias[c + 1]);
                }
            }
            if (MODE == 2) {
                rs += __shfl_xor_sync(0xFFFFFFFFu, rs, 1);
                rs += __shfl_xor_sync(0xFFFFFFFFu, rs, 2);
                if ((lane & 3) == 0) atomicAdd(Rp + r, rs);
            }
        }
    }
}

// ---------------- prep: inputs -> fp16; zero accumulators ----------------
__global__ void prep_inputs(const float* __restrict__ q, const float* __restrict__ k,
                            const float* __restrict__ v,
                            fp16* __restrict__ qh, fp16* __restrict__ kh,
                            fp16* __restrict__ vh,
                            float* __restrict__ r, float* __restrict__ t,
                            float* __restrict__ cs) {
    size_t i = ((size_t)blockIdx.x * 256 + threadIdx.x) * 4;
    const float* X = (blockIdx.y == 0) ? q : (blockIdx.y == 1) ? k : v;
    fp16* H = (blockIdx.y == 0) ? qh : (blockIdx.y == 1) ? kh : vh;
    float4 val = *(const float4*)(X + i);
    *(__half2*)(H + i)     = __halves2half2(__float2half(val.x), __float2half(val.y));
    *(__half2*)(H + i + 2) = __halves2half2(__float2half(val.z), __float2half(val.w));
    if (blockIdx.y == 0) {
        if (blockIdx.x < SEQ / 1024)
            *(float4*)(r + blockIdx.x * 1024 + threadIdx.x * 4) = make_float4(0,0,0,0);
        if (blockIdx.x == 4) { float4 z = make_float4(0,0,0,0);
            *(float4*)(t + threadIdx.x * 4) = z; }
        if (blockIdx.x == 5) { float4 z = make_float4(0,0,0,0);
            *(float4*)(cs + threadIdx.x * 4) = z; }
    }
}

// ---------------- prep: W -> W^T fp16 ----------------
__global__ void prep_weights(const float* __restrict__ Wq, const float* __restrict__ Wk,
                             const float* __restrict__ Wv,
                             fp16* __restrict__ TQ, fp16* __restrict__ TK,
                             fp16* __restrict__ TV) {
    __shared__ float t[32][33];
    const float* W = (blockIdx.z == 0) ? Wq : (blockIdx.z == 1) ? Wk : Wv;
    fp16* TH = (blockIdx.z == 0) ? TQ : (blockIdx.z == 1) ? TK : TV;
    int k0 = blockIdx.y * 32, n0 = blockIdx.x * 32;
    int tx = threadIdx.x, ty = threadIdx.y;
    for (int r = ty; r < 32; r += 8) t[r][tx] = W[(size_t)(k0 + r) * DIM + n0 + tx];
    __syncthreads();
    for (int r = ty; r < 32; r += 8)
        TH[(size_t)(n0 + r) * DIM + (k0 + tx)] = __float2half(t[tx][r]);
}

// ---------------- s0 = sum_j 1/(4096+r[j]) ----------------
__global__ void s0_kernel(const float* __restrict__ r, float* __restrict__ s0) {
    float s = 0.f;
    for (int i = threadIdx.x; i < SEQ; i += 256) s += 1.0f / (4096.0f + r[i]);
    __shared__ float sm[8];
#pragma unroll
    for (int o = 16; o > 0; o >>= 1) s += __shfl_down_sync(0xFFFFFFFFu, s, o);
    if ((threadIdx.x & 31) == 0) sm[threadIdx.x >> 5] = s;
    __syncthreads();
    if (threadIdx.x < 8) {
        s = sm[threadIdx.x];
#pragma unroll
        for (int o = 4; o > 0; o >>= 1) s += __shfl_down_sync(0xFFu, s, o);
        if (threadIdx.x == 0) *s0 = s;
    }
}

// ---------------- t[d] += sum_{j in block} value[j][d]/(4096+r[j]) ----------------
__global__ void colsum_t(const float* __restrict__ value, const float* __restrict__ r,
                         float* __restrict__ t) {
    __shared__ float rinv[128];
    int d = blockIdx.x * 256 + threadIdx.x;
    int j0 = blockIdx.y * 128;
    if (threadIdx.x < 128) rinv[threadIdx.x] = 1.0f / (4096.0f + r[j0 + threadIdx.x]);
    __syncthreads();
    float s = 0.f;
#pragma unroll 4
    for (int j = 0; j < 128; j++)
        s += value[(size_t)(j0 + j) * DIM + d] * rinv[j];
    atomicAdd(t + d, s);
}

// ---------------- cs[d] += sum_{k in block} t[k]*Wv[k][d] (+ bv[d]*s0 once) --------
__global__ void colsum_cs(const float* __restrict__ t, const float* __restrict__ Wv,
                          const float* __restrict__ bv, const float* __restrict__ s0,
                          float* __restrict__ cs) {
    __shared__ float ts[128];
    int d = blockIdx.x * 256 + threadIdx.x;
    int k0 = blockIdx.y * 128;
    if (threadIdx.x < 128) ts[threadIdx.x] = t[k0 + threadIdx.x];
    __syncthreads();
    float s = 0.f;
#pragma unroll 4
    for (int k = 0; k < 128; k++)
        s += ts[k] * Wv[(size_t)(k0 + k) * DIM + d];
    if (blockIdx.y == 0) s += bv[d] * (*s0);
    atomicAdd(cs + d, s);
}

// ---------------- V''T[d][j] = VTh[d][j] * 4096/(4096+r[j]) ----------------
__global__ void scale_kernel(const fp16* __restrict__ VTh, const float* __restrict__ r,
                             fp16* __restrict__ VTs) {
    size_t i = ((size_t)blockIdx.x * 256 + threadIdx.x) * 4;
    int j = (int)(i % SEQ);
    float4 rr = *(const float4*)(r + j);
    __half2 h0 = *(const __half2*)(VTh + i);
    __half2 h1 = *(const __half2*)(VTh + i + 2);
    float2 f0 = __half22float2(h0), f1 = __half22float2(h1);
    f0.x *= 4096.0f / (4096.0f + rr.x);
    f0.y *= 4096.0f / (4096.0f + rr.y);
    f1.x *= 4096.0f / (4096.0f + rr.z);
    f1.y *= 4096.0f / (4096.0f + rr.w);
    *(__half2*)(VTs + i)     = __halves2half2(__float2half(f0.x), __float2half(f0.y));
    *(__half2*)(VTs + i + 2) = __halves2half2(__float2half(f1.x), __float2half(f1.y));
}

// ---------------- launch ----------------
extern "C" void kernel_launch(void* const* d_in, const int* in_sizes, int n_in,
                              void* d_out, int out_size) {
    const float* query = (const float*)d_in[0];
    const float* key   = (const float*)d_in[1];
    const float* value = (const float*)d_in[2];
    const float* Wq    = (const float*)d_in[3];
    const float* bq    = (const float*)d_in[4];
    const float* Wk    = (const float*)d_in[5];
    const float* bk    = (const float*)d_in[6];
    const float* Wv    = (const float*)d_in[7];
    const float* bv    = (const float*)d_in[8];
    float* out = (float*)d_out;

    fp16 *xqh,*xkh,*xvh,*WqTh,*WkTh,*WvTh,*Qh,*Kh,*VTh,*VTs,*F;
    float *r,*t,*cs,*s0;
    cudaGetSymbolAddress((void**)&xqh, g_xqh);
    cudaGetSymbolAddress((void**)&xkh, g_xkh);
    cudaGetSymbolAddress((void**)&xvh, g_xvh);
    cudaGetSymbolAddress((void**)&WqTh, g_WqTh);
    cudaGetSymbolAddress((void**)&WkTh, g_WkTh);
    cudaGetSymbolAddress((void**)&WvTh, g_WvTh);
    cudaGetSymbolAddress((void**)&Qh, g_Qh);
    cudaGetSymbolAddress((void**)&Kh, g_Kh);
    cudaGetSymbolAddress((void**)&VTh, g_VTh);
    cudaGetSymbolAddress((void**)&VTs, g_VTs);
    cudaGetSymbolAddress((void**)&F, g_F);
    cudaGetSymbolAddress((void**)&r, g_r);
    cudaGetSymbolAddress((void**)&t, g_t);
    cudaGetSymbolAddress((void**)&cs, g_cs);
    cudaGetSymbolAddress((void**)&s0, g_s0);

    cudaFuncSetAttribute(gemm_mma<1024,0>, cudaFuncAttributeMaxDynamicSharedMemorySize, SMEM_DYN);
    cudaFuncSetAttribute(gemm_mma<1024,4>, cudaFuncAttributeMaxDynamicSharedMemorySize, SMEM_DYN);
    cudaFuncSetAttribute(gemm_mma<1024,2>, cudaFuncAttributeMaxDynamicSharedMemorySize, SMEM_DYN);
    cudaFuncSetAttribute(gemm_mma<4096,3>, cudaFuncAttributeMaxDynamicSharedMemorySize, SMEM_DYN);

    // (0) inputs -> fp16; zero r/t/cs
    prep_inputs<<<dim3(SEQ*DIM/1024, 3), 256>>>(query, key, value, xqh, xkh, xvh, r, t, cs);
    // (1) weights -> W^T fp16
    prep_weights<<<dim3(DIM/32, DIM/32, 3), dim3(32, 8)>>>(Wq, Wk, Wv, WqTh, WkTh, WvTh);

    // (2,3) Q,K projections
    gemm_mma<1024,0><<<dim3(DIM/256, SEQ/128), 256, SMEM_DYN>>>(
        xqh, WqTh, bq, nullptr, Qh, DIM);
    gemm_mma<1024,0><<<dim3(DIM/256, SEQ/128), 256, SMEM_DYN>>>(
        xkh, WkTh, bk, nullptr, Kh, DIM);

    // (4) V^T = WvT @ value^T + bv[m]  (single-pass fp16, [DIM,SEQ])
    gemm_mma<1024,4><<<dim3(SEQ/256, DIM/128), 256, SMEM_DYN>>>(
        WvTh, xvh, bv, nullptr, VTh, SEQ);

    // (5) F = expm1((Q@K^T)/1024), fused rowsum  <- ncu -s 5
    gemm_mma<1024,2><<<dim3(SEQ/256, SEQ/128), 256, SMEM_DYN>>>(
        Qh, Kh, nullptr, r, F, SEQ);

    // (6-9) exact colsum via rank-1 path + V'' scaling
    s0_kernel<<<1, 256>>>(r, s0);
    colsum_t<<<dim3(DIM/256, SEQ/128), 256>>>(value, r, t);
    scale_kernel<<<(int)((size_t)DIM*SEQ/1024), 256>>>(VTh, r, VTs);
    colsum_cs<<<dim3(DIM/256, DIM/128), 256>>>(t, Wv, bv, s0, cs);

    // (10) out = F @ V'' / 4096 + cs
    gemm_mma<4096,3><<<dim3(DIM/256, SEQ/128), 256, SMEM_DYN>>>(
        F, VTs, cs, nullptr, out, DIM);
}